// round 1
// baseline (speedup 1.0000x reference)
#include <cuda_runtime.h>

#define N_NODES 131072
#define N_EDGES 524288
#define N_GRAPHS 4096
#define DIM_IN 128
#define DIM_H 512
#define DIM_OUT 256
#define BN_EPS 1e-5f

// ---------------- scratch (device globals; no allocation allowed) -------------
__device__ float g_bufA[(size_t)N_NODES * DIM_H];
__device__ float g_bufB[(size_t)N_NODES * DIM_H];
__device__ float g_pooled[N_GRAPHS * DIM_OUT];
__device__ float g_f1[N_GRAPHS * DIM_OUT];
__device__ int   g_degc[N_NODES];
__device__ int   g_rowptr[N_NODES + 1];
__device__ int   g_cursor[N_NODES];
__device__ int   g_colsrc[N_EDGES];
__device__ float g_normv[N_EDGES];
__device__ float g_dinv[N_NODES];
__device__ int   g_blksum[128];
__device__ int   g_blkoff[128];

// ---------------- graph preprocessing ----------------------------------------
__global__ void zero_degc_kernel() {
    int i = blockIdx.x * blockDim.x + threadIdx.x;
    if (i < N_NODES) g_degc[i] = 0;
}

__global__ void count_kernel(const int* __restrict__ dst) {
    int e = blockIdx.x * blockDim.x + threadIdx.x;
    if (e < N_EDGES) atomicAdd(&g_degc[dst[e]], 1);
}

__global__ void dinv_kernel() {
    int i = blockIdx.x * blockDim.x + threadIdx.x;
    if (i < N_NODES) g_dinv[i] = rsqrtf((float)(g_degc[i] + 1));  // +1 self loop
}

// inclusive scan of degc within 1024-chunks -> g_cursor (temp), block sums
__global__ void scan_p1_kernel() {
    __shared__ int s[1024];
    int i = blockIdx.x * 1024 + threadIdx.x;
    int v = g_degc[i];
    s[threadIdx.x] = v;
    __syncthreads();
    for (int off = 1; off < 1024; off <<= 1) {
        int t = (threadIdx.x >= off) ? s[threadIdx.x - off] : 0;
        __syncthreads();
        s[threadIdx.x] += t;
        __syncthreads();
    }
    g_cursor[i] = s[threadIdx.x];           // inclusive scan within chunk
    if (threadIdx.x == 1023) g_blksum[blockIdx.x] = s[1023];
}

__global__ void scan_p2_kernel() {
    __shared__ int s[128];
    int t = threadIdx.x;
    s[t] = g_blksum[t];
    __syncthreads();
    for (int off = 1; off < 128; off <<= 1) {
        int v = (t >= off) ? s[t - off] : 0;
        __syncthreads();
        s[t] += v;
        __syncthreads();
    }
    g_blkoff[t] = (t == 0) ? 0 : s[t - 1];  // exclusive block offsets
}

__global__ void scan_p3_kernel() {
    int i = blockIdx.x * blockDim.x + threadIdx.x;
    if (i < N_NODES) {
        int excl = g_cursor[i] - g_degc[i] + g_blkoff[i >> 10];
        g_rowptr[i] = excl;
        g_cursor[i] = excl;
        if (i == N_NODES - 1) g_rowptr[N_NODES] = excl + g_degc[i];
    }
}

__global__ void fill_kernel(const int* __restrict__ src, const int* __restrict__ dst) {
    int e = blockIdx.x * blockDim.x + threadIdx.x;
    if (e < N_EDGES) {
        int s = src[e], d = dst[e];
        int p = atomicAdd(&g_cursor[d], 1);
        g_colsrc[p] = s;
        g_normv[p]  = g_dinv[s] * g_dinv[d];
    }
}

// ---------------- SGEMM: C[M,Nn] = A[M,K] @ B[K,Nn] ---------------------------
// 128x128x8 tile, 256 threads, 8x8 micro-tile per thread.
// mode: 0 = plain, 1 = bias+relu, 2 = bias
__global__ __launch_bounds__(256) void sgemm_kernel(
    const float* __restrict__ A, const float* __restrict__ B, float* __restrict__ C,
    int M, int Nn, int K, const float* __restrict__ bias, int mode)
{
    const int BM = 128, BN = 128, BK = 8;
    __shared__ float As[BK][BM];
    __shared__ float Bs[BK][BN];
    int tid = threadIdx.x;
    int bx = blockIdx.x;   // N tile
    int by = blockIdx.y;   // M tile

    const float* Ab = A + (size_t)by * BM * K;
    const float* Bb = B + (size_t)bx * BN;

    int arow = tid >> 1;            // 0..127
    int acol = (tid & 1) * 4;       // 0 or 4
    int brow = tid >> 5;            // 0..7
    int bcol = (tid & 31) * 4;      // 0..124
    int ty = (tid >> 4) * 8;        // 0..120
    int tx = (tid & 15) * 8;        // 0..120

    float acc[8][8];
#pragma unroll
    for (int i = 0; i < 8; i++)
#pragma unroll
        for (int j = 0; j < 8; j++) acc[i][j] = 0.f;

    for (int k0 = 0; k0 < K; k0 += BK) {
        float4 av = *(const float4*)(Ab + (size_t)arow * K + k0 + acol);
        As[acol + 0][arow] = av.x;
        As[acol + 1][arow] = av.y;
        As[acol + 2][arow] = av.z;
        As[acol + 3][arow] = av.w;
        float4 bv = *(const float4*)(Bb + (size_t)(k0 + brow) * Nn + bcol);
        *(float4*)&Bs[brow][bcol] = bv;
        __syncthreads();

#pragma unroll
        for (int k = 0; k < BK; k++) {
            float4 a0 = *(const float4*)&As[k][ty];
            float4 a1 = *(const float4*)&As[k][ty + 4];
            float4 b0 = *(const float4*)&Bs[k][tx];
            float4 b1 = *(const float4*)&Bs[k][tx + 4];
            float ra[8] = {a0.x, a0.y, a0.z, a0.w, a1.x, a1.y, a1.z, a1.w};
            float rb[8] = {b0.x, b0.y, b0.z, b0.w, b1.x, b1.y, b1.z, b1.w};
#pragma unroll
            for (int i = 0; i < 8; i++)
#pragma unroll
                for (int j = 0; j < 8; j++) acc[i][j] = fmaf(ra[i], rb[j], acc[i][j]);
        }
        __syncthreads();
    }

    int crow0 = by * BM + ty;
    int ccol  = bx * BN + tx;
    float bias0[8] = {0, 0, 0, 0, 0, 0, 0, 0};
    if (mode != 0) {
        float4 c0 = *(const float4*)(bias + ccol);
        float4 c1 = *(const float4*)(bias + ccol + 4);
        bias0[0] = c0.x; bias0[1] = c0.y; bias0[2] = c0.z; bias0[3] = c0.w;
        bias0[4] = c1.x; bias0[5] = c1.y; bias0[6] = c1.z; bias0[7] = c1.w;
    }
#pragma unroll
    for (int i = 0; i < 8; i++) {
        float* Crow = C + (size_t)(crow0 + i) * Nn + ccol;
        float v[8];
#pragma unroll
        for (int j = 0; j < 8; j++) {
            float z = acc[i][j] + bias0[j];
            if (mode == 1) z = fmaxf(z, 0.f);
            v[j] = z;
        }
        *(float4*)(Crow)     = make_float4(v[0], v[1], v[2], v[3]);
        *(float4*)(Crow + 4) = make_float4(v[4], v[5], v[6], v[7]);
    }
}

// ---------------- aggregation: out = bn(relu(segsum(norm*h[src]) + b)) --------
template <int D>
__global__ void agg_kernel(const float* __restrict__ hin, float* __restrict__ hout,
                           const float* __restrict__ bias, const float* __restrict__ gam,
                           const float* __restrict__ bet,  const float* __restrict__ mu,
                           const float* __restrict__ var)
{
    const int V = D / 4;
    int n = blockIdx.x;
    int t = threadIdx.x;
    const float4* h4 = (const float4*)hin;

    float din = g_dinv[n];
    float wself = din * din;
    float4 a = h4[(size_t)n * V + t];
    float ax = a.x * wself, ay = a.y * wself, az = a.z * wself, aw = a.w * wself;

    int e = g_rowptr[n], end = g_rowptr[n + 1];
    for (; e < end; e++) {
        int s = g_colsrc[e];
        float w = g_normv[e];
        float4 v = h4[(size_t)s * V + t];
        ax = fmaf(w, v.x, ax);
        ay = fmaf(w, v.y, ay);
        az = fmaf(w, v.z, az);
        aw = fmaf(w, v.w, aw);
    }

    int c = t * 4;
    float4 b4 = *(const float4*)(bias + c);
    float4 gg = *(const float4*)(gam + c);
    float4 bb = *(const float4*)(bet + c);
    float4 mm = *(const float4*)(mu + c);
    float4 vv = *(const float4*)(var + c);

    ax = fmaxf(ax + b4.x, 0.f);
    ay = fmaxf(ay + b4.y, 0.f);
    az = fmaxf(az + b4.z, 0.f);
    aw = fmaxf(aw + b4.w, 0.f);

    float4 o;
    o.x = gg.x * (ax - mm.x) * rsqrtf(vv.x + BN_EPS) + bb.x;
    o.y = gg.y * (ay - mm.y) * rsqrtf(vv.y + BN_EPS) + bb.y;
    o.z = gg.z * (az - mm.z) * rsqrtf(vv.z + BN_EPS) + bb.z;
    o.w = gg.w * (aw - mm.w) * rsqrtf(vv.w + BN_EPS) + bb.w;
    ((float4*)hout)[(size_t)n * V + t] = o;
}

// ---------------- mean pool over sorted batch ---------------------------------
__device__ __forceinline__ int lowerb(const int* __restrict__ b, int n, int v) {
    int lo = 0, hi = n;
    while (lo < hi) {
        int m = (lo + hi) >> 1;
        if (b[m] < v) lo = m + 1; else hi = m;
    }
    return lo;
}

__global__ void pool_kernel(const float* __restrict__ h, const int* __restrict__ batch,
                            float* __restrict__ pooled)
{
    __shared__ int s_lo, s_hi;
    int g = blockIdx.x;
    if (threadIdx.x == 0) {
        s_lo = lowerb(batch, N_NODES, g);
        s_hi = lowerb(batch, N_NODES, g + 1);
    }
    __syncthreads();
    int lo = s_lo, hi = s_hi;
    const float4* h4 = (const float4*)h;
    float4 acc = make_float4(0.f, 0.f, 0.f, 0.f);
    for (int r = lo; r < hi; r++) {
        float4 v = h4[(size_t)r * (DIM_OUT / 4) + threadIdx.x];
        acc.x += v.x; acc.y += v.y; acc.z += v.z; acc.w += v.w;
    }
    float inv = 1.f / fmaxf((float)(hi - lo), 1.f);
    acc.x *= inv; acc.y *= inv; acc.z *= inv; acc.w *= inv;
    ((float4*)pooled)[g * (DIM_OUT / 4) + threadIdx.x] = acc;
}

// ---------------- launch ------------------------------------------------------
extern "C" void kernel_launch(void* const* d_in, const int* in_sizes, int n_in,
                              void* d_out, int out_size)
{
    const float* x   = (const float*)d_in[0];
    const int*   ei  = (const int*)d_in[1];
    const int*   bat = (const int*)d_in[2];
    const float* W1  = (const float*)d_in[3];
    const float* b1  = (const float*)d_in[4];
    const float* W2  = (const float*)d_in[5];
    const float* b2  = (const float*)d_in[6];
    const float* W3  = (const float*)d_in[7];
    const float* b3  = (const float*)d_in[8];
    const float* g1  = (const float*)d_in[9];
    const float* be1 = (const float*)d_in[10];
    const float* m1  = (const float*)d_in[11];
    const float* v1  = (const float*)d_in[12];
    const float* g2  = (const float*)d_in[13];
    const float* be2 = (const float*)d_in[14];
    const float* m2  = (const float*)d_in[15];
    const float* v2  = (const float*)d_in[16];
    const float* g3  = (const float*)d_in[17];
    const float* be3 = (const float*)d_in[18];
    const float* m3  = (const float*)d_in[19];
    const float* v3  = (const float*)d_in[20];
    const float* Wf1 = (const float*)d_in[21];
    const float* bf1 = (const float*)d_in[22];
    const float* Wf2 = (const float*)d_in[23];
    const float* bf2 = (const float*)d_in[24];

    const int* src = ei;
    const int* dst = ei + N_EDGES;

    float *bufA, *bufB, *pooled, *f1;
    cudaGetSymbolAddress((void**)&bufA,   g_bufA);
    cudaGetSymbolAddress((void**)&bufB,   g_bufB);
    cudaGetSymbolAddress((void**)&pooled, g_pooled);
    cudaGetSymbolAddress((void**)&f1,     g_f1);

    // ---- graph preprocessing (CSR by dst + norm weights) ----
    zero_degc_kernel<<<N_NODES / 256, 256>>>();
    count_kernel<<<N_EDGES / 256, 256>>>(dst);
    dinv_kernel<<<N_NODES / 256, 256>>>();
    scan_p1_kernel<<<128, 1024>>>();
    scan_p2_kernel<<<1, 128>>>();
    scan_p3_kernel<<<N_NODES / 256, 256>>>();
    fill_kernel<<<N_EDGES / 256, 256>>>(src, dst);

    // ---- layer 1: x@W1 -> agg+bias+relu+bn ----
    {
        dim3 grid(DIM_H / 128, N_NODES / 128);
        sgemm_kernel<<<grid, 256>>>(x, W1, bufA, N_NODES, DIM_H, DIM_IN, nullptr, 0);
        agg_kernel<DIM_H><<<N_NODES, DIM_H / 4>>>(bufA, bufB, b1, g1, be1, m1, v1);
    }
    // ---- layer 2 ----
    {
        dim3 grid(DIM_H / 128, N_NODES / 128);
        sgemm_kernel<<<grid, 256>>>(bufB, W2, bufA, N_NODES, DIM_H, DIM_H, nullptr, 0);
        agg_kernel<DIM_H><<<N_NODES, DIM_H / 4>>>(bufA, bufB, b2, g2, be2, m2, v2);
    }
    // ---- layer 3 ----
    {
        dim3 grid(DIM_OUT / 128, N_NODES / 128);
        sgemm_kernel<<<grid, 256>>>(bufB, W3, bufA, N_NODES, DIM_OUT, DIM_H, nullptr, 0);
        agg_kernel<DIM_OUT><<<N_NODES, DIM_OUT / 4>>>(bufA, bufB, b3, g3, be3, m3, v3);
    }
    // ---- mean pool ----
    pool_kernel<<<N_GRAPHS, DIM_OUT / 4>>>(bufB, bat, pooled);

    // ---- MLP head ----
    {
        dim3 grid(DIM_OUT / 128, N_GRAPHS / 128);
        sgemm_kernel<<<grid, 256>>>(pooled, Wf1, f1, N_GRAPHS, DIM_OUT, DIM_OUT, bf1, 1);
        sgemm_kernel<<<grid, 256>>>(f1, Wf2, (float*)d_out, N_GRAPHS, DIM_OUT, DIM_OUT, bf2, 2);
    }
}

// round 3
// speedup vs baseline: 2.1362x; 2.1362x over previous
#include <cuda_runtime.h>
#include <cstdint>

#define N_NODES 131072
#define N_EDGES 524288
#define N_GRAPHS 4096
#define DIM_IN 128
#define DIM_H 512
#define DIM_OUT 256
#define BN_EPS 1e-5f

// ---------------- scratch (device globals; no allocation allowed) -------------
__device__ float g_bufA[(size_t)N_NODES * DIM_H];
__device__ float g_bufB[(size_t)N_NODES * DIM_H];
__device__ float g_pooled[N_GRAPHS * DIM_OUT];
__device__ float g_f1[N_GRAPHS * DIM_OUT];
__device__ int   g_degc[N_NODES];
__device__ int   g_rowptr[N_NODES + 1];
__device__ int   g_cursor[N_NODES];
__device__ int   g_colsrc[N_EDGES];
__device__ float g_normv[N_EDGES];
__device__ float g_dinv[N_NODES];
__device__ int   g_blksum[128];
__device__ int   g_blkoff[128];

// ---------------- graph preprocessing ----------------------------------------
__global__ void zero_degc_kernel() {
    int i = blockIdx.x * blockDim.x + threadIdx.x;
    if (i < N_NODES) g_degc[i] = 0;
}

__global__ void count_kernel(const int* __restrict__ dst) {
    int e = blockIdx.x * blockDim.x + threadIdx.x;
    if (e < N_EDGES) atomicAdd(&g_degc[dst[e]], 1);
}

__global__ void dinv_kernel() {
    int i = blockIdx.x * blockDim.x + threadIdx.x;
    if (i < N_NODES) g_dinv[i] = rsqrtf((float)(g_degc[i] + 1));  // +1 self loop
}

__global__ void scan_p1_kernel() {
    __shared__ int s[1024];
    int i = blockIdx.x * 1024 + threadIdx.x;
    int v = g_degc[i];
    s[threadIdx.x] = v;
    __syncthreads();
    for (int off = 1; off < 1024; off <<= 1) {
        int t = (threadIdx.x >= off) ? s[threadIdx.x - off] : 0;
        __syncthreads();
        s[threadIdx.x] += t;
        __syncthreads();
    }
    g_cursor[i] = s[threadIdx.x];
    if (threadIdx.x == 1023) g_blksum[blockIdx.x] = s[1023];
}

__global__ void scan_p2_kernel() {
    __shared__ int s[128];
    int t = threadIdx.x;
    s[t] = g_blksum[t];
    __syncthreads();
    for (int off = 1; off < 128; off <<= 1) {
        int v = (t >= off) ? s[t - off] : 0;
        __syncthreads();
        s[t] += v;
        __syncthreads();
    }
    g_blkoff[t] = (t == 0) ? 0 : s[t - 1];
}

__global__ void scan_p3_kernel() {
    int i = blockIdx.x * blockDim.x + threadIdx.x;
    if (i < N_NODES) {
        int excl = g_cursor[i] - g_degc[i] + g_blkoff[i >> 10];
        g_rowptr[i] = excl;
        g_cursor[i] = excl;
        if (i == N_NODES - 1) g_rowptr[N_NODES] = excl + g_degc[i];
    }
}

__global__ void fill_kernel(const int* __restrict__ src, const int* __restrict__ dst) {
    int e = blockIdx.x * blockDim.x + threadIdx.x;
    if (e < N_EDGES) {
        int s = src[e], d = dst[e];
        int p = atomicAdd(&g_cursor[d], 1);
        g_colsrc[p] = s;
        g_normv[p]  = g_dinv[s] * g_dinv[d];
    }
}

// ---------------- TF32 tensor-core GEMM ---------------------------------------
// C[M,Nn] = A[M,K] @ B[K,Nn]; optional fused epilogue:
//   bias != null: z += bias[col];  relu_flag: z = max(z,0);
//   var  != null: z = g*rsqrt(v+eps)*z + (be - g*rsqrt(v+eps)*m)
// BM=BN=128, BK=16, 256 threads, 8 warps (4x2), warp tile 32x64, mma m16n8k8.
__device__ __forceinline__ uint32_t f2tf32(float f) {
    uint32_t r;
    asm("cvt.rna.tf32.f32 %0, %1;" : "=r"(r) : "f"(f));
    return r;
}

#define MMA_TF32(d, a, b0, b1)                                                   \
    asm volatile("mma.sync.aligned.m16n8k8.row.col.f32.tf32.tf32.f32 "          \
        "{%0,%1,%2,%3}, {%4,%5,%6,%7}, {%8,%9}, {%0,%1,%2,%3};"                 \
        : "+f"(d[0]), "+f"(d[1]), "+f"(d[2]), "+f"(d[3])                        \
        : "r"(a[0]), "r"(a[1]), "r"(a[2]), "r"(a[3]), "r"(b0), "r"(b1))

__global__ __launch_bounds__(256, 2) void tgemm_kernel(
    const float* __restrict__ A, const float* __restrict__ B, float* __restrict__ C,
    int M, int Nn, int K,
    const float* __restrict__ bias, const float* __restrict__ gam,
    const float* __restrict__ bet,  const float* __restrict__ mu,
    const float* __restrict__ var,  int relu_flag)
{
    const int BM = 128, BN = 128, BK = 16;
    const int ASTR = 20, BSTR = 132;                // bank-tuned strides
    __shared__ float As[BM * ASTR];                 // [m][k]
    __shared__ float Bs[BK * BSTR];                 // [k][n]

    int tid  = threadIdx.x;
    int lane = tid & 31, warp = tid >> 5;
    int wm = warp & 3, wn = warp >> 2;              // 4 x 2 warp grid
    int gid = lane >> 2, tig = lane & 3;

    const float* Ab = A + (size_t)blockIdx.y * BM * K;
    const float* Bb = B + (size_t)blockIdx.x * BN;

    int a_row[2], a_col[2], b_row[2], b_col[2];
#pragma unroll
    for (int i = 0; i < 2; i++) {
        int s = tid + i * 256;                      // 512 float4 slots per tile
        a_row[i] = s >> 2;  a_col[i] = (s & 3) * 4;     // A: 128 x 16
        b_row[i] = s >> 5;  b_col[i] = (s & 31) * 4;    // B: 16 x 128
    }

    float acc[2][8][4];
#pragma unroll
    for (int mi = 0; mi < 2; mi++)
#pragma unroll
        for (int ni = 0; ni < 8; ni++)
#pragma unroll
            for (int j = 0; j < 4; j++) acc[mi][ni][j] = 0.f;

    float4 pa[2], pb[2];
#pragma unroll
    for (int i = 0; i < 2; i++) {
        pa[i] = *(const float4*)(Ab + (size_t)a_row[i] * K + a_col[i]);
        pb[i] = *(const float4*)(Bb + (size_t)b_row[i] * Nn + b_col[i]);
    }

    for (int k0 = 0; k0 < K; k0 += BK) {
        // commit prefetched tile to smem (round to tf32 here)
#pragma unroll
        for (int i = 0; i < 2; i++) {
            float* pA = &As[a_row[i] * ASTR + a_col[i]];
            pA[0] = __uint_as_float(f2tf32(pa[i].x));
            pA[1] = __uint_as_float(f2tf32(pa[i].y));
            pA[2] = __uint_as_float(f2tf32(pa[i].z));
            pA[3] = __uint_as_float(f2tf32(pa[i].w));
            float* pB = &Bs[b_row[i] * BSTR + b_col[i]];
            pB[0] = __uint_as_float(f2tf32(pb[i].x));
            pB[1] = __uint_as_float(f2tf32(pb[i].y));
            pB[2] = __uint_as_float(f2tf32(pb[i].z));
            pB[3] = __uint_as_float(f2tf32(pb[i].w));
        }
        __syncthreads();

        if (k0 + BK < K) {                           // prefetch next tile
#pragma unroll
            for (int i = 0; i < 2; i++) {
                pa[i] = *(const float4*)(Ab + (size_t)a_row[i] * K + (k0 + BK) + a_col[i]);
                pb[i] = *(const float4*)(Bb + (size_t)(k0 + BK + b_row[i]) * Nn + b_col[i]);
            }
        }

#pragma unroll
        for (int ks = 0; ks < BK; ks += 8) {
            uint32_t af[2][4];
#pragma unroll
            for (int mi = 0; mi < 2; mi++) {
                int rb = wm * 32 + mi * 16;
                af[mi][0] = __float_as_uint(As[(rb + gid)     * ASTR + ks + tig]);
                af[mi][1] = __float_as_uint(As[(rb + gid + 8) * ASTR + ks + tig]);
                af[mi][2] = __float_as_uint(As[(rb + gid)     * ASTR + ks + tig + 4]);
                af[mi][3] = __float_as_uint(As[(rb + gid + 8) * ASTR + ks + tig + 4]);
            }
#pragma unroll
            for (int ni = 0; ni < 8; ni++) {
                int nb = wn * 64 + ni * 8;
                uint32_t b0 = __float_as_uint(Bs[(ks + tig)     * BSTR + nb + gid]);
                uint32_t b1 = __float_as_uint(Bs[(ks + tig + 4) * BSTR + nb + gid]);
                MMA_TF32(acc[0][ni], af[0], b0, b1);
                MMA_TF32(acc[1][ni], af[1], b0, b1);
            }
        }
        __syncthreads();
    }

    // epilogue
    int row0 = blockIdx.y * BM + wm * 32 + gid;
#pragma unroll
    for (int ni = 0; ni < 8; ni++) {
        int c = blockIdx.x * BN + wn * 64 + ni * 8 + 2 * tig;
        float bz0 = 0.f, bz1 = 0.f, s0 = 1.f, s1 = 1.f, sh0 = 0.f, sh1 = 0.f;
        if (bias) { float2 b2 = *(const float2*)(bias + c); bz0 = b2.x; bz1 = b2.y; }
        if (var) {
            float2 gg = *(const float2*)(gam + c);
            float2 vv = *(const float2*)(var + c);
            float2 mm = *(const float2*)(mu  + c);
            float2 bb = *(const float2*)(bet + c);
            s0 = gg.x * rsqrtf(vv.x + BN_EPS);  s1 = gg.y * rsqrtf(vv.y + BN_EPS);
            sh0 = bb.x - s0 * mm.x;             sh1 = bb.y - s1 * mm.y;
        }
#pragma unroll
        for (int mi = 0; mi < 2; mi++) {
            int r = row0 + mi * 16;
            float f0 = acc[mi][ni][0] + bz0, f1 = acc[mi][ni][1] + bz1;
            float f2 = acc[mi][ni][2] + bz0, f3 = acc[mi][ni][3] + bz1;
            if (relu_flag) {
                f0 = fmaxf(f0, 0.f); f1 = fmaxf(f1, 0.f);
                f2 = fmaxf(f2, 0.f); f3 = fmaxf(f3, 0.f);
            }
            if (var) {
                f0 = s0 * f0 + sh0; f1 = s1 * f1 + sh1;
                f2 = s0 * f2 + sh0; f3 = s1 * f3 + sh1;
            }
            *(float2*)(C + (size_t)r * Nn + c)        = make_float2(f0, f1);
            *(float2*)(C + (size_t)(r + 8) * Nn + c)  = make_float2(f2, f3);
        }
    }
}

// ---------------- aggregation kernels -----------------------------------------
// plain: out[n] = dinv[n]^2 * h[n] + sum_e norm[e] * h[src[e]]
template <int D>
__global__ void aggp_kernel(const float* __restrict__ hin, float* __restrict__ hout)
{
    const int V = D / 4;
    int n = blockIdx.x;
    int t = threadIdx.x;
    const float4* h4 = (const float4*)hin;

    float din = g_dinv[n];
    float wself = din * din;
    float4 a = h4[(size_t)n * V + t];
    float ax = a.x * wself, ay = a.y * wself, az = a.z * wself, aw = a.w * wself;

    int e = g_rowptr[n], end = g_rowptr[n + 1];
    for (; e < end; e++) {
        int s = g_colsrc[e];
        float w = g_normv[e];
        float4 v = h4[(size_t)s * V + t];
        ax = fmaf(w, v.x, ax);
        ay = fmaf(w, v.y, ay);
        az = fmaf(w, v.z, az);
        aw = fmaf(w, v.w, aw);
    }
    ((float4*)hout)[(size_t)n * V + t] = make_float4(ax, ay, az, aw);
}

// epilogue version: out = bn(relu(agg + b))
template <int D>
__global__ void agg_kernel(const float* __restrict__ hin, float* __restrict__ hout,
                           const float* __restrict__ bias, const float* __restrict__ gam,
                           const float* __restrict__ bet,  const float* __restrict__ mu,
                           const float* __restrict__ var)
{
    const int V = D / 4;
    int n = blockIdx.x;
    int t = threadIdx.x;
    const float4* h4 = (const float4*)hin;

    float din = g_dinv[n];
    float wself = din * din;
    float4 a = h4[(size_t)n * V + t];
    float ax = a.x * wself, ay = a.y * wself, az = a.z * wself, aw = a.w * wself;

    int e = g_rowptr[n], end = g_rowptr[n + 1];
    for (; e < end; e++) {
        int s = g_colsrc[e];
        float w = g_normv[e];
        float4 v = h4[(size_t)s * V + t];
        ax = fmaf(w, v.x, ax);
        ay = fmaf(w, v.y, ay);
        az = fmaf(w, v.z, az);
        aw = fmaf(w, v.w, aw);
    }

    int c = t * 4;
    float4 b4 = *(const float4*)(bias + c);
    float4 gg = *(const float4*)(gam + c);
    float4 bb = *(const float4*)(bet + c);
    float4 mm = *(const float4*)(mu + c);
    float4 vv = *(const float4*)(var + c);

    ax = fmaxf(ax + b4.x, 0.f);
    ay = fmaxf(ay + b4.y, 0.f);
    az = fmaxf(az + b4.z, 0.f);
    aw = fmaxf(aw + b4.w, 0.f);

    float4 o;
    o.x = gg.x * (ax - mm.x) * rsqrtf(vv.x + BN_EPS) + bb.x;
    o.y = gg.y * (ay - mm.y) * rsqrtf(vv.y + BN_EPS) + bb.y;
    o.z = gg.z * (az - mm.z) * rsqrtf(vv.z + BN_EPS) + bb.z;
    o.w = gg.w * (aw - mm.w) * rsqrtf(vv.w + BN_EPS) + bb.w;
    ((float4*)hout)[(size_t)n * V + t] = o;
}

// ---------------- mean pool over sorted batch ---------------------------------
__device__ __forceinline__ int lowerb(const int* __restrict__ b, int n, int v) {
    int lo = 0, hi = n;
    while (lo < hi) {
        int m = (lo + hi) >> 1;
        if (b[m] < v) lo = m + 1; else hi = m;
    }
    return lo;
}

__global__ void pool_kernel(const float* __restrict__ h, const int* __restrict__ batch,
                            float* __restrict__ pooled)
{
    __shared__ int s_lo, s_hi;
    int g = blockIdx.x;
    if (threadIdx.x == 0) {
        s_lo = lowerb(batch, N_NODES, g);
        s_hi = lowerb(batch, N_NODES, g + 1);
    }
    __syncthreads();
    int lo = s_lo, hi = s_hi;
    const float4* h4 = (const float4*)h;
    float4 acc = make_float4(0.f, 0.f, 0.f, 0.f);
    for (int r = lo; r < hi; r++) {
        float4 v = h4[(size_t)r * (DIM_OUT / 4) + threadIdx.x];
        acc.x += v.x; acc.y += v.y; acc.z += v.z; acc.w += v.w;
    }
    float inv = 1.f / fmaxf((float)(hi - lo), 1.f);
    acc.x *= inv; acc.y *= inv; acc.z *= inv; acc.w *= inv;
    ((float4*)pooled)[g * (DIM_OUT / 4) + threadIdx.x] = acc;
}

// ---------------- launch ------------------------------------------------------
extern "C" void kernel_launch(void* const* d_in, const int* in_sizes, int n_in,
                              void* d_out, int out_size)
{
    const float* x   = (const float*)d_in[0];
    const int*   ei  = (const int*)d_in[1];
    const int*   bat = (const int*)d_in[2];
    const float* W1  = (const float*)d_in[3];
    const float* b1  = (const float*)d_in[4];
    const float* W2  = (const float*)d_in[5];
    const float* b2  = (const float*)d_in[6];
    const float* W3  = (const float*)d_in[7];
    const float* b3  = (const float*)d_in[8];
    const float* g1  = (const float*)d_in[9];
    const float* be1 = (const float*)d_in[10];
    const float* m1  = (const float*)d_in[11];
    const float* v1  = (const float*)d_in[12];
    const float* g2  = (const float*)d_in[13];
    const float* be2 = (const float*)d_in[14];
    const float* m2  = (const float*)d_in[15];
    const float* v2  = (const float*)d_in[16];
    const float* g3  = (const float*)d_in[17];
    const float* be3 = (const float*)d_in[18];
    const float* m3  = (const float*)d_in[19];
    const float* v3  = (const float*)d_in[20];
    const float* Wf1 = (const float*)d_in[21];
    const float* bf1 = (const float*)d_in[22];
    const float* Wf2 = (const float*)d_in[23];
    const float* bf2 = (const float*)d_in[24];

    const int* src = ei;
    const int* dst = ei + N_EDGES;

    float *bufA, *bufB, *pooled, *f1;
    cudaGetSymbolAddress((void**)&bufA,   g_bufA);
    cudaGetSymbolAddress((void**)&bufB,   g_bufB);
    cudaGetSymbolAddress((void**)&pooled, g_pooled);
    cudaGetSymbolAddress((void**)&f1,     g_f1);

    // ---- graph preprocessing (CSR by dst + norm weights) ----
    zero_degc_kernel<<<N_NODES / 256, 256>>>();
    count_kernel<<<N_EDGES / 256, 256>>>(dst);
    dinv_kernel<<<N_NODES / 256, 256>>>();
    scan_p1_kernel<<<128, 1024>>>();
    scan_p2_kernel<<<1, 128>>>();
    scan_p3_kernel<<<N_NODES / 256, 256>>>();
    fill_kernel<<<N_EDGES / 256, 256>>>(src, dst);

    // ---- layer 1: agg(x) [dim 128] -> GEMM 128->512 with fused bias+relu+bn ----
    aggp_kernel<DIM_IN><<<N_NODES, DIM_IN / 4>>>(x, bufA);
    {
        dim3 grid(DIM_H / 128, N_NODES / 128);
        tgemm_kernel<<<grid, 256>>>(bufA, W1, bufB, N_NODES, DIM_H, DIM_IN,
                                    b1, g1, be1, m1, v1, 1);
    }
    // ---- layer 2: agg(h) [512] -> GEMM 512->512 with fused epilogue ----
    aggp_kernel<DIM_H><<<N_NODES, DIM_H / 4>>>(bufB, bufA);
    {
        dim3 grid(DIM_H / 128, N_NODES / 128);
        tgemm_kernel<<<grid, 256>>>(bufA, W2, bufB, N_NODES, DIM_H, DIM_H,
                                    b2, g2, be2, m2, v2, 1);
    }
    // ---- layer 3: GEMM 512->256 plain -> agg [256] with epilogue ----
    {
        dim3 grid(DIM_OUT / 128, N_NODES / 128);
        tgemm_kernel<<<grid, 256>>>(bufB, W3, bufA, N_NODES, DIM_OUT, DIM_H,
                                    nullptr, nullptr, nullptr, nullptr, nullptr, 0);
    }
    agg_kernel<DIM_OUT><<<N_NODES, DIM_OUT / 4>>>(bufA, bufB, b3, g3, be3, m3, v3);

    // ---- mean pool ----
    pool_kernel<<<N_GRAPHS, DIM_OUT / 4>>>(bufB, bat, pooled);

    // ---- MLP head (tensor GEMMs) ----
    {
        dim3 grid(DIM_OUT / 128, N_GRAPHS / 128);
        tgemm_kernel<<<grid, 256>>>(pooled, Wf1, f1, N_GRAPHS, DIM_OUT, DIM_OUT,
                                    bf1, nullptr, nullptr, nullptr, nullptr, 1);
        tgemm_kernel<<<grid, 256>>>(f1, Wf2, (float*)d_out, N_GRAPHS, DIM_OUT, DIM_OUT,
                                    bf2, nullptr, nullptr, nullptr, nullptr, 0);
    }
}

// round 4
// speedup vs baseline: 2.2519x; 1.0542x over previous
#include <cuda_runtime.h>
#include <cstdint>

#define N_NODES 131072
#define N_EDGES 524288
#define N_GRAPHS 4096
#define DIM_IN 128
#define DIM_H 512
#define DIM_OUT 256
#define BN_EPS 1e-5f

// ---------------- scratch (device globals; no allocation allowed) -------------
__device__ float g_bufA[(size_t)N_NODES * DIM_H];
__device__ float g_bufB[(size_t)N_NODES * DIM_H];
__device__ float g_pooled[N_GRAPHS * DIM_OUT];
__device__ float g_f1[N_GRAPHS * DIM_OUT];
__device__ float g_wr[589824];          // tf32-rounded weights, concatenated
__device__ int   g_degc[N_NODES];
__device__ int   g_rowptr[N_NODES + 1];
__device__ int   g_cursor[N_NODES];
__device__ int   g_colsrc[N_EDGES];
__device__ float g_normv[N_EDGES];
__device__ float g_dinv[N_NODES];
__device__ int   g_blksum[128];
__device__ int   g_blkoff[128];

// weight offsets in g_wr
#define OW1  0
#define OW2  65536
#define OW3  327680
#define OWF1 458752
#define OWF2 524288
#define NWTOT 589824

__device__ __forceinline__ uint32_t f2tf32(float f) {
    uint32_t r;
    asm("cvt.rna.tf32.f32 %0, %1;" : "=r"(r) : "f"(f));
    return r;
}
__device__ __forceinline__ float rtf32(float f) { return __uint_as_float(f2tf32(f)); }

// ---------------- graph preprocessing ----------------------------------------
__global__ void zero_degc_kernel() {
    int i = blockIdx.x * blockDim.x + threadIdx.x;
    if (i < N_NODES) g_degc[i] = 0;
}

__global__ void count_kernel(const int* __restrict__ dst) {
    int e = blockIdx.x * blockDim.x + threadIdx.x;
    if (e < N_EDGES) atomicAdd(&g_degc[dst[e]], 1);
}

__global__ void scan_p1_kernel() {
    __shared__ int s[1024];
    int i = blockIdx.x * 1024 + threadIdx.x;
    int v = g_degc[i];
    s[threadIdx.x] = v;
    __syncthreads();
    for (int off = 1; off < 1024; off <<= 1) {
        int t = (threadIdx.x >= off) ? s[threadIdx.x - off] : 0;
        __syncthreads();
        s[threadIdx.x] += t;
        __syncthreads();
    }
    g_cursor[i] = s[threadIdx.x];
    if (threadIdx.x == 1023) g_blksum[blockIdx.x] = s[1023];
}

__global__ void scan_p2_kernel() {
    __shared__ int s[128];
    int t = threadIdx.x;
    s[t] = g_blksum[t];
    __syncthreads();
    for (int off = 1; off < 128; off <<= 1) {
        int v = (t >= off) ? s[t - off] : 0;
        __syncthreads();
        s[t] += v;
        __syncthreads();
    }
    g_blkoff[t] = (t == 0) ? 0 : s[t - 1];
}

__global__ void scan_p3_kernel() {   // also computes dinv
    int i = blockIdx.x * blockDim.x + threadIdx.x;
    if (i < N_NODES) {
        int d = g_degc[i];
        int excl = g_cursor[i] - d + g_blkoff[i >> 10];
        g_rowptr[i] = excl;
        g_cursor[i] = excl;
        g_dinv[i] = rsqrtf((float)(d + 1));
        if (i == N_NODES - 1) g_rowptr[N_NODES] = excl + d;
    }
}

__global__ void fill_kernel(const int* __restrict__ src, const int* __restrict__ dst) {
    int e = blockIdx.x * blockDim.x + threadIdx.x;
    if (e < N_EDGES) {
        int s = src[e], d = dst[e];
        int p = atomicAdd(&g_cursor[d], 1);
        g_colsrc[p] = s;
        g_normv[p]  = g_dinv[s] * g_dinv[d];
    }
}

// ---------------- weight rounding (tf32 RNA, one pass) ------------------------
__global__ void round_w_kernel(const float* __restrict__ W1, const float* __restrict__ W2,
                               const float* __restrict__ W3, const float* __restrict__ Wf1,
                               const float* __restrict__ Wf2)
{
    int i = blockIdx.x * blockDim.x + threadIdx.x;
    if (i >= NWTOT) return;
    float v;
    if      (i < OW2)  v = W1[i - OW1];
    else if (i < OW3)  v = W2[i - OW2];
    else if (i < OWF1) v = W3[i - OW3];
    else if (i < OWF2) v = Wf1[i - OWF1];
    else               v = Wf2[i - OWF2];
    g_wr[i] = rtf32(v);
}

// ---------------- TF32 tensor-core GEMM, cp.async 2-stage pipeline ------------
// C[M,Nn] = A[M,K] @ B[K,Nn]; A,B must be tf32-pre-rounded fp32.
// epilogue: bias/relu/bn as before; round_out: round stored values to tf32.
#define MMA_TF32(d, a, b0, b1)                                                   \
    asm volatile("mma.sync.aligned.m16n8k8.row.col.f32.tf32.tf32.f32 "          \
        "{%0,%1,%2,%3}, {%4,%5,%6,%7}, {%8,%9}, {%0,%1,%2,%3};"                 \
        : "+f"(d[0]), "+f"(d[1]), "+f"(d[2]), "+f"(d[3])                        \
        : "r"(a[0]), "r"(a[1]), "r"(a[2]), "r"(a[3]), "r"(b0), "r"(b1))

__device__ __forceinline__ void cpa16(uint32_t dst, const float* src) {
    asm volatile("cp.async.ca.shared.global [%0], [%1], 16;" :: "r"(dst), "l"(src));
}

__global__ __launch_bounds__(256, 2) void tgemm_kernel(
    const float* __restrict__ A, const float* __restrict__ B, float* __restrict__ C,
    int M, int Nn, int K,
    const float* __restrict__ bias, const float* __restrict__ gam,
    const float* __restrict__ bet,  const float* __restrict__ mu,
    const float* __restrict__ var,  int relu_flag, int round_out)
{
    const int BM = 128, BN = 128, BK = 16;
    const int ASTR = 20, BSTR = 132;                // bank-tuned strides
    __shared__ float As[2][BM * ASTR];              // [m][k]
    __shared__ float Bs[2][BK * BSTR];              // [k][n]

    int tid  = threadIdx.x;
    int lane = tid & 31, warp = tid >> 5;
    int wm = warp & 3, wn = warp >> 2;              // 4 x 2 warp grid
    int gid = lane >> 2, tig = lane & 3;

    const float* Ab = A + (size_t)blockIdx.y * BM * K;
    const float* Bb = B + (size_t)blockIdx.x * BN;

    int a_row[2], a_col[2], b_row[2], b_col[2];
    uint32_t a_sm[2], b_sm[2];
#pragma unroll
    for (int i = 0; i < 2; i++) {
        int s = tid + i * 256;                      // 512 float4 slots per tile
        a_row[i] = s >> 2;  a_col[i] = (s & 3) * 4;     // A: 128 x 16
        b_row[i] = s >> 5;  b_col[i] = (s & 31) * 4;    // B: 16 x 128
        a_sm[i] = (uint32_t)__cvta_generic_to_shared(&As[0][a_row[i] * ASTR + a_col[i]]);
        b_sm[i] = (uint32_t)__cvta_generic_to_shared(&Bs[0][b_row[i] * BSTR + b_col[i]]);
    }
    const uint32_t aStageB = (uint32_t)(BM * ASTR * 4);
    const uint32_t bStageB = (uint32_t)(BK * BSTR * 4);

    float acc[2][8][4];
#pragma unroll
    for (int mi = 0; mi < 2; mi++)
#pragma unroll
        for (int ni = 0; ni < 8; ni++)
#pragma unroll
            for (int j = 0; j < 4; j++) acc[mi][ni][j] = 0.f;

    // stage 0 load
#pragma unroll
    for (int i = 0; i < 2; i++) {
        cpa16(a_sm[i], Ab + (size_t)a_row[i] * K + a_col[i]);
        cpa16(b_sm[i], Bb + (size_t)b_row[i] * Nn + b_col[i]);
    }
    asm volatile("cp.async.commit_group;");

    int nIter = K / BK;
    for (int it = 0; it < nIter; it++) {
        int stg = it & 1;
        if (it + 1 < nIter) {
            int k0 = (it + 1) * BK;
            uint32_t so = (uint32_t)((it + 1) & 1);
#pragma unroll
            for (int i = 0; i < 2; i++) {
                cpa16(a_sm[i] + so * aStageB, Ab + (size_t)a_row[i] * K + k0 + a_col[i]);
                cpa16(b_sm[i] + so * bStageB, Bb + (size_t)(k0 + b_row[i]) * Nn + b_col[i]);
            }
        }
        asm volatile("cp.async.commit_group;");
        asm volatile("cp.async.wait_group 1;");
        __syncthreads();

        const float* Asb = As[stg];
        const float* Bsb = Bs[stg];
#pragma unroll
        for (int ks = 0; ks < BK; ks += 8) {
            uint32_t af[2][4];
#pragma unroll
            for (int mi = 0; mi < 2; mi++) {
                int rb = wm * 32 + mi * 16;
                af[mi][0] = __float_as_uint(Asb[(rb + gid)     * ASTR + ks + tig]);
                af[mi][1] = __float_as_uint(Asb[(rb + gid + 8) * ASTR + ks + tig]);
                af[mi][2] = __float_as_uint(Asb[(rb + gid)     * ASTR + ks + tig + 4]);
                af[mi][3] = __float_as_uint(Asb[(rb + gid + 8) * ASTR + ks + tig + 4]);
            }
#pragma unroll
            for (int ni = 0; ni < 8; ni++) {
                int nb = wn * 64 + ni * 8;
                uint32_t b0 = __float_as_uint(Bsb[(ks + tig)     * BSTR + nb + gid]);
                uint32_t b1 = __float_as_uint(Bsb[(ks + tig + 4) * BSTR + nb + gid]);
                MMA_TF32(acc[0][ni], af[0], b0, b1);
                MMA_TF32(acc[1][ni], af[1], b0, b1);
            }
        }
        __syncthreads();
    }

    // epilogue
    int row0 = blockIdx.y * BM + wm * 32 + gid;
#pragma unroll
    for (int ni = 0; ni < 8; ni++) {
        int c = blockIdx.x * BN + wn * 64 + ni * 8 + 2 * tig;
        float bz0 = 0.f, bz1 = 0.f, s0 = 1.f, s1 = 1.f, sh0 = 0.f, sh1 = 0.f;
        if (bias) { float2 b2 = *(const float2*)(bias + c); bz0 = b2.x; bz1 = b2.y; }
        if (var) {
            float2 gg = *(const float2*)(gam + c);
            float2 vv = *(const float2*)(var + c);
            float2 mm = *(const float2*)(mu  + c);
            float2 bb = *(const float2*)(bet + c);
            s0 = gg.x * rsqrtf(vv.x + BN_EPS);  s1 = gg.y * rsqrtf(vv.y + BN_EPS);
            sh0 = bb.x - s0 * mm.x;             sh1 = bb.y - s1 * mm.y;
        }
#pragma unroll
        for (int mi = 0; mi < 2; mi++) {
            int r = row0 + mi * 16;
            float f0 = acc[mi][ni][0] + bz0, f1 = acc[mi][ni][1] + bz1;
            float f2 = acc[mi][ni][2] + bz0, f3 = acc[mi][ni][3] + bz1;
            if (relu_flag) {
                f0 = fmaxf(f0, 0.f); f1 = fmaxf(f1, 0.f);
                f2 = fmaxf(f2, 0.f); f3 = fmaxf(f3, 0.f);
            }
            if (var) {
                f0 = s0 * f0 + sh0; f1 = s1 * f1 + sh1;
                f2 = s0 * f2 + sh0; f3 = s1 * f3 + sh1;
            }
            if (round_out) {
                f0 = rtf32(f0); f1 = rtf32(f1); f2 = rtf32(f2); f3 = rtf32(f3);
            }
            *(float2*)(C + (size_t)r * Nn + c)        = make_float2(f0, f1);
            *(float2*)(C + (size_t)(r + 8) * Nn + c)  = make_float2(f2, f3);
        }
    }
}

// ---------------- aggregation kernels -----------------------------------------
// plain (feeds a GEMM A operand -> round output to tf32):
// out[n] = round( dinv[n]^2 * h[n] + sum_e norm[e] * h[src[e]] )
template <int D>
__global__ void aggp_kernel(const float* __restrict__ hin, float* __restrict__ hout)
{
    const int V = D / 4;
    int n = blockIdx.x;
    int t = threadIdx.x;
    const float4* h4 = (const float4*)hin;

    float din = g_dinv[n];
    float wself = din * din;
    float4 a = h4[(size_t)n * V + t];
    float ax = a.x * wself, ay = a.y * wself, az = a.z * wself, aw = a.w * wself;

    int e = g_rowptr[n], end = g_rowptr[n + 1];
    for (; e < end; e++) {
        int s = g_colsrc[e];
        float w = g_normv[e];
        float4 v = h4[(size_t)s * V + t];
        ax = fmaf(w, v.x, ax);
        ay = fmaf(w, v.y, ay);
        az = fmaf(w, v.z, az);
        aw = fmaf(w, v.w, aw);
    }
    ((float4*)hout)[(size_t)n * V + t] =
        make_float4(rtf32(ax), rtf32(ay), rtf32(az), rtf32(aw));
}

// epilogue version (final layer, feeds pool -> stay fp32): out = bn(relu(agg + b))
template <int D>
__global__ void agg_kernel(const float* __restrict__ hin, float* __restrict__ hout,
                           const float* __restrict__ bias, const float* __restrict__ gam,
                           const float* __restrict__ bet,  const float* __restrict__ mu,
                           const float* __restrict__ var)
{
    const int V = D / 4;
    int n = blockIdx.x;
    int t = threadIdx.x;
    const float4* h4 = (const float4*)hin;

    float din = g_dinv[n];
    float wself = din * din;
    float4 a = h4[(size_t)n * V + t];
    float ax = a.x * wself, ay = a.y * wself, az = a.z * wself, aw = a.w * wself;

    int e = g_rowptr[n], end = g_rowptr[n + 1];
    for (; e < end; e++) {
        int s = g_colsrc[e];
        float w = g_normv[e];
        float4 v = h4[(size_t)s * V + t];
        ax = fmaf(w, v.x, ax);
        ay = fmaf(w, v.y, ay);
        az = fmaf(w, v.z, az);
        aw = fmaf(w, v.w, aw);
    }

    int c = t * 4;
    float4 b4 = *(const float4*)(bias + c);
    float4 gg = *(const float4*)(gam + c);
    float4 bb = *(const float4*)(bet + c);
    float4 mm = *(const float4*)(mu + c);
    float4 vv = *(const float4*)(var + c);

    ax = fmaxf(ax + b4.x, 0.f);
    ay = fmaxf(ay + b4.y, 0.f);
    az = fmaxf(az + b4.z, 0.f);
    aw = fmaxf(aw + b4.w, 0.f);

    float4 o;
    o.x = gg.x * (ax - mm.x) * rsqrtf(vv.x + BN_EPS) + bb.x;
    o.y = gg.y * (ay - mm.y) * rsqrtf(vv.y + BN_EPS) + bb.y;
    o.z = gg.z * (az - mm.z) * rsqrtf(vv.z + BN_EPS) + bb.z;
    o.w = gg.w * (aw - mm.w) * rsqrtf(vv.w + BN_EPS) + bb.w;
    ((float4*)hout)[(size_t)n * V + t] = o;
}

// ---------------- mean pool over sorted batch (rounds output: feeds head GEMM) -
__device__ __forceinline__ int lowerb(const int* __restrict__ b, int n, int v) {
    int lo = 0, hi = n;
    while (lo < hi) {
        int m = (lo + hi) >> 1;
        if (b[m] < v) lo = m + 1; else hi = m;
    }
    return lo;
}

__global__ void pool_kernel(const float* __restrict__ h, const int* __restrict__ batch,
                            float* __restrict__ pooled)
{
    __shared__ int s_lo, s_hi;
    int g = blockIdx.x;
    if (threadIdx.x == 0) {
        s_lo = lowerb(batch, N_NODES, g);
        s_hi = lowerb(batch, N_NODES, g + 1);
    }
    __syncthreads();
    int lo = s_lo, hi = s_hi;
    const float4* h4 = (const float4*)h;
    float4 acc = make_float4(0.f, 0.f, 0.f, 0.f);
    for (int r = lo; r < hi; r++) {
        float4 v = h4[(size_t)r * (DIM_OUT / 4) + threadIdx.x];
        acc.x += v.x; acc.y += v.y; acc.z += v.z; acc.w += v.w;
    }
    float inv = 1.f / fmaxf((float)(hi - lo), 1.f);
    ((float4*)pooled)[g * (DIM_OUT / 4) + threadIdx.x] =
        make_float4(rtf32(acc.x * inv), rtf32(acc.y * inv),
                    rtf32(acc.z * inv), rtf32(acc.w * inv));
}

// ---------------- launch ------------------------------------------------------
extern "C" void kernel_launch(void* const* d_in, const int* in_sizes, int n_in,
                              void* d_out, int out_size)
{
    const float* x   = (const float*)d_in[0];
    const int*   ei  = (const int*)d_in[1];
    const int*   bat = (const int*)d_in[2];
    const float* W1  = (const float*)d_in[3];
    const float* b1  = (const float*)d_in[4];
    const float* W2  = (const float*)d_in[5];
    const float* b2  = (const float*)d_in[6];
    const float* W3  = (const float*)d_in[7];
    const float* b3  = (const float*)d_in[8];
    const float* g1  = (const float*)d_in[9];
    const float* be1 = (const float*)d_in[10];
    const float* m1  = (const float*)d_in[11];
    const float* v1  = (const float*)d_in[12];
    const float* g2  = (const float*)d_in[13];
    const float* be2 = (const float*)d_in[14];
    const float* m2  = (const float*)d_in[15];
    const float* v2  = (const float*)d_in[16];
    const float* g3  = (const float*)d_in[17];
    const float* be3 = (const float*)d_in[18];
    const float* m3  = (const float*)d_in[19];
    const float* v3  = (const float*)d_in[20];
    const float* Wf1 = (const float*)d_in[21];
    const float* bf1 = (const float*)d_in[22];
    const float* Wf2 = (const float*)d_in[23];
    const float* bf2 = (const float*)d_in[24];

    const int* src = ei;
    const int* dst = ei + N_EDGES;

    float *bufA, *bufB, *pooled, *f1, *wr;
    cudaGetSymbolAddress((void**)&bufA,   g_bufA);
    cudaGetSymbolAddress((void**)&bufB,   g_bufB);
    cudaGetSymbolAddress((void**)&pooled, g_pooled);
    cudaGetSymbolAddress((void**)&f1,     g_f1);
    cudaGetSymbolAddress((void**)&wr,     g_wr);

    // ---- graph preprocessing + weight rounding ----
    zero_degc_kernel<<<N_NODES / 256, 256>>>();
    count_kernel<<<N_EDGES / 256, 256>>>(dst);
    scan_p1_kernel<<<128, 1024>>>();
    scan_p2_kernel<<<1, 128>>>();
    scan_p3_kernel<<<N_NODES / 256, 256>>>();
    fill_kernel<<<N_EDGES / 256, 256>>>(src, dst);
    round_w_kernel<<<(NWTOT + 255) / 256, 256>>>(W1, W2, W3, Wf1, Wf2);

    // ---- layer 1: agg(x) [dim 128] -> GEMM 128->512 fused bias+relu+bn ----
    aggp_kernel<DIM_IN><<<N_NODES, DIM_IN / 4>>>(x, bufA);
    {
        dim3 grid(DIM_H / 128, N_NODES / 128);
        tgemm_kernel<<<grid, 256>>>(bufA, wr + OW1, bufB, N_NODES, DIM_H, DIM_IN,
                                    b1, g1, be1, m1, v1, 1, 0);
    }
    // ---- layer 2: agg(h) [512] -> GEMM 512->512 fused epilogue (+round for L3) ----
    aggp_kernel<DIM_H><<<N_NODES, DIM_H / 4>>>(bufB, bufA);
    {
        dim3 grid(DIM_H / 128, N_NODES / 128);
        tgemm_kernel<<<grid, 256>>>(bufA, wr + OW2, bufB, N_NODES, DIM_H, DIM_H,
                                    b2, g2, be2, m2, v2, 1, 1);
    }
    // ---- layer 3: GEMM 512->256 plain -> agg [256] with epilogue ----
    {
        dim3 grid(DIM_OUT / 128, N_NODES / 128);
        tgemm_kernel<<<grid, 256>>>(bufB, wr + OW3, bufA, N_NODES, DIM_OUT, DIM_H,
                                    nullptr, nullptr, nullptr, nullptr, nullptr, 0, 0);
    }
    agg_kernel<DIM_OUT><<<N_NODES, DIM_OUT / 4>>>(bufA, bufB, b3, g3, be3, m3, v3);

    // ---- mean pool (rounds output for head GEMM) ----
    pool_kernel<<<N_GRAPHS, DIM_OUT / 4>>>(bufB, bat, pooled);

    // ---- MLP head ----
    {
        dim3 grid(DIM_OUT / 128, N_GRAPHS / 128);
        tgemm_kernel<<<grid, 256>>>(pooled, wr + OWF1, f1, N_GRAPHS, DIM_OUT, DIM_OUT,
                                    bf1, nullptr, nullptr, nullptr, nullptr, 1, 1);
        tgemm_kernel<<<grid, 256>>>(f1, wr + OWF2, (float*)d_out, N_GRAPHS, DIM_OUT, DIM_OUT,
                                    bf2, nullptr, nullptr, nullptr, nullptr, 0, 0);
    }
}

// round 5
// speedup vs baseline: 2.3324x; 1.0357x over previous
#include <cuda_runtime.h>
#include <cstdint>

#define N_NODES 131072
#define N_EDGES 524288
#define N_GRAPHS 4096
#define DIM_IN 128
#define DIM_H 512
#define DIM_OUT 256
#define BN_EPS 1e-5f

// ---------------- scratch (device globals; no allocation allowed) -------------
__device__ float g_bufA[(size_t)N_NODES * DIM_H];
__device__ float g_bufB[(size_t)N_NODES * DIM_H];
__device__ float g_pooled[N_GRAPHS * DIM_OUT];
__device__ float g_f1[N_GRAPHS * DIM_OUT];
__device__ float g_wr[589824];          // tf32-rounded weights, concatenated
__device__ int   g_degc[N_NODES];
__device__ int   g_rowptr[N_NODES + 1];
__device__ int   g_cursor[N_NODES];
__device__ int   g_colsrc[N_EDGES];
__device__ float g_normv[N_EDGES];
__device__ float g_dinv[N_NODES];
__device__ int   g_blksum[128];
__device__ int   g_blkoff[128];

// weight offsets in g_wr
#define OW1  0
#define OW2  65536
#define OW3  327680
#define OWF1 458752
#define OWF2 524288
#define NWTOT 589824

__device__ __forceinline__ uint32_t f2tf32(float f) {
    uint32_t r;
    asm("cvt.rna.tf32.f32 %0, %1;" : "=r"(r) : "f"(f));
    return r;
}
__device__ __forceinline__ float rtf32(float f) { return __uint_as_float(f2tf32(f)); }

// ---------------- graph preprocessing ----------------------------------------
__global__ void zero_degc_kernel() {
    int i = blockIdx.x * blockDim.x + threadIdx.x;
    if (i < N_NODES) g_degc[i] = 0;
}

__global__ void count_kernel(const int* __restrict__ dst) {
    int e = blockIdx.x * blockDim.x + threadIdx.x;
    if (e < N_EDGES) atomicAdd(&g_degc[dst[e]], 1);
}

__global__ void scan_p1_kernel() {
    __shared__ int s[1024];
    int i = blockIdx.x * 1024 + threadIdx.x;
    int v = g_degc[i];
    s[threadIdx.x] = v;
    __syncthreads();
    for (int off = 1; off < 1024; off <<= 1) {
        int t = (threadIdx.x >= off) ? s[threadIdx.x - off] : 0;
        __syncthreads();
        s[threadIdx.x] += t;
        __syncthreads();
    }
    g_cursor[i] = s[threadIdx.x];
    if (threadIdx.x == 1023) g_blksum[blockIdx.x] = s[1023];
}

__global__ void scan_p2_kernel() {
    __shared__ int s[128];
    int t = threadIdx.x;
    s[t] = g_blksum[t];
    __syncthreads();
    for (int off = 1; off < 128; off <<= 1) {
        int v = (t >= off) ? s[t - off] : 0;
        __syncthreads();
        s[t] += v;
        __syncthreads();
    }
    g_blkoff[t] = (t == 0) ? 0 : s[t - 1];
}

__global__ void scan_p3_kernel() {   // also computes dinv
    int i = blockIdx.x * blockDim.x + threadIdx.x;
    if (i < N_NODES) {
        int d = g_degc[i];
        int excl = g_cursor[i] - d + g_blkoff[i >> 10];
        g_rowptr[i] = excl;
        g_cursor[i] = excl;
        g_dinv[i] = rsqrtf((float)(d + 1));
        if (i == N_NODES - 1) g_rowptr[N_NODES] = excl + d;
    }
}

__global__ void fill_kernel(const int* __restrict__ src, const int* __restrict__ dst) {
    int e = blockIdx.x * blockDim.x + threadIdx.x;
    if (e < N_EDGES) {
        int s = src[e], d = dst[e];
        int p = atomicAdd(&g_cursor[d], 1);
        g_colsrc[p] = s;
        g_normv[p]  = g_dinv[s] * g_dinv[d];
    }
}

// ---------------- weight rounding (tf32 RNA, one pass) ------------------------
__global__ void round_w_kernel(const float* __restrict__ W1, const float* __restrict__ W2,
                               const float* __restrict__ W3, const float* __restrict__ Wf1,
                               const float* __restrict__ Wf2)
{
    int i = blockIdx.x * blockDim.x + threadIdx.x;
    if (i >= NWTOT) return;
    float v;
    if      (i < OW2)  v = W1[i - OW1];
    else if (i < OW3)  v = W2[i - OW2];
    else if (i < OWF1) v = W3[i - OW3];
    else if (i < OWF2) v = Wf1[i - OWF1];
    else               v = Wf2[i - OWF2];
    g_wr[i] = rtf32(v);
}

// ---------------- TF32 tensor-core GEMM, 3-stage cp.async pipeline ------------
// C[M,Nn] = A[M,K] @ B[K,Nn]; A,B must be tf32-pre-rounded fp32.
#define MMA_TF32(d, a, b0, b1)                                                   \
    asm volatile("mma.sync.aligned.m16n8k8.row.col.f32.tf32.tf32.f32 "          \
        "{%0,%1,%2,%3}, {%4,%5,%6,%7}, {%8,%9}, {%0,%1,%2,%3};"                 \
        : "+f"(d[0]), "+f"(d[1]), "+f"(d[2]), "+f"(d[3])                        \
        : "r"(a[0]), "r"(a[1]), "r"(a[2]), "r"(a[3]), "r"(b0), "r"(b1))

__device__ __forceinline__ void cpa16(uint32_t dst, const float* src) {
    asm volatile("cp.async.ca.shared.global [%0], [%1], 16;" :: "r"(dst), "l"(src));
}

__global__ __launch_bounds__(256, 2) void tgemm_kernel(
    const float* __restrict__ A, const float* __restrict__ B, float* __restrict__ C,
    int M, int Nn, int K,
    const float* __restrict__ bias, const float* __restrict__ gam,
    const float* __restrict__ bet,  const float* __restrict__ mu,
    const float* __restrict__ var,  int relu_flag, int round_out)
{
    const int BM = 128, BN = 128, BK = 16;
    const int ASTR = 20, BSTR = 132;                // bank-tuned strides
    __shared__ float As[3][BM * ASTR];              // [m][k]
    __shared__ float Bs[3][BK * BSTR];              // [k][n]

    int tid  = threadIdx.x;
    int lane = tid & 31, warp = tid >> 5;
    int wm = warp & 3, wn = warp >> 2;              // 4 x 2 warp grid
    int gid = lane >> 2, tig = lane & 3;

    const float* Ab = A + (size_t)blockIdx.y * BM * K;
    const float* Bb = B + (size_t)blockIdx.x * BN;

    int a_row[2], a_col[2], b_row[2], b_col[2];
    uint32_t a_sm[2], b_sm[2];
#pragma unroll
    for (int i = 0; i < 2; i++) {
        int s = tid + i * 256;                      // 512 float4 slots per tile
        a_row[i] = s >> 2;  a_col[i] = (s & 3) * 4;     // A: 128 x 16
        b_row[i] = s >> 5;  b_col[i] = (s & 31) * 4;    // B: 16 x 128
        a_sm[i] = (uint32_t)__cvta_generic_to_shared(&As[0][a_row[i] * ASTR + a_col[i]]);
        b_sm[i] = (uint32_t)__cvta_generic_to_shared(&Bs[0][b_row[i] * BSTR + b_col[i]]);
    }
    const uint32_t aStageB = (uint32_t)(BM * ASTR * 4);
    const uint32_t bStageB = (uint32_t)(BK * BSTR * 4);

    float acc[2][8][4];
#pragma unroll
    for (int mi = 0; mi < 2; mi++)
#pragma unroll
        for (int ni = 0; ni < 8; ni++)
#pragma unroll
            for (int j = 0; j < 4; j++) acc[mi][ni][j] = 0.f;

    int nIter = K / BK;
    // prologue: stages 0 and 1
#pragma unroll
    for (int st = 0; st < 2; st++) {
        int k0 = st * BK;
#pragma unroll
        for (int i = 0; i < 2; i++) {
            cpa16(a_sm[i] + st * aStageB, Ab + (size_t)a_row[i] * K + k0 + a_col[i]);
            cpa16(b_sm[i] + st * bStageB, Bb + (size_t)(k0 + b_row[i]) * Nn + b_col[i]);
        }
        asm volatile("cp.async.commit_group;");
    }

    for (int it = 0; it < nIter; it++) {
        int stg = it % 3;
        asm volatile("cp.async.wait_group 1;");
        __syncthreads();

        const float* Asb = As[stg];
        const float* Bsb = Bs[stg];
#pragma unroll
        for (int ks = 0; ks < BK; ks += 8) {
            uint32_t af[2][4];
#pragma unroll
            for (int mi = 0; mi < 2; mi++) {
                int rb = wm * 32 + mi * 16;
                af[mi][0] = __float_as_uint(Asb[(rb + gid)     * ASTR + ks + tig]);
                af[mi][1] = __float_as_uint(Asb[(rb + gid + 8) * ASTR + ks + tig]);
                af[mi][2] = __float_as_uint(Asb[(rb + gid)     * ASTR + ks + tig + 4]);
                af[mi][3] = __float_as_uint(Asb[(rb + gid + 8) * ASTR + ks + tig + 4]);
            }
#pragma unroll
            for (int ni = 0; ni < 8; ni++) {
                int nb = wn * 64 + ni * 8;
                uint32_t b0 = __float_as_uint(Bsb[(ks + tig)     * BSTR + nb + gid]);
                uint32_t b1 = __float_as_uint(Bsb[(ks + tig + 4) * BSTR + nb + gid]);
                MMA_TF32(acc[0][ni], af[0], b0, b1);
                MMA_TF32(acc[1][ni], af[1], b0, b1);
            }
        }

        // issue stage it+2 AFTER compute: previous-iteration sync guards WAR
        if (it + 2 < nIter) {
            int k0 = (it + 2) * BK;
            uint32_t so = (uint32_t)((it + 2) % 3);
#pragma unroll
            for (int i = 0; i < 2; i++) {
                cpa16(a_sm[i] + so * aStageB, Ab + (size_t)a_row[i] * K + k0 + a_col[i]);
                cpa16(b_sm[i] + so * bStageB, Bb + (size_t)(k0 + b_row[i]) * Nn + b_col[i]);
            }
        }
        asm volatile("cp.async.commit_group;");
    }

    // epilogue
    int row0 = blockIdx.y * BM + wm * 32 + gid;
#pragma unroll
    for (int ni = 0; ni < 8; ni++) {
        int c = blockIdx.x * BN + wn * 64 + ni * 8 + 2 * tig;
        float bz0 = 0.f, bz1 = 0.f, s0 = 1.f, s1 = 1.f, sh0 = 0.f, sh1 = 0.f;
        if (bias) { float2 b2 = *(const float2*)(bias + c); bz0 = b2.x; bz1 = b2.y; }
        if (var) {
            float2 gg = *(const float2*)(gam + c);
            float2 vv = *(const float2*)(var + c);
            float2 mm = *(const float2*)(mu  + c);
            float2 bb = *(const float2*)(bet + c);
            s0 = gg.x * rsqrtf(vv.x + BN_EPS);  s1 = gg.y * rsqrtf(vv.y + BN_EPS);
            sh0 = bb.x - s0 * mm.x;             sh1 = bb.y - s1 * mm.y;
        }
#pragma unroll
        for (int mi = 0; mi < 2; mi++) {
            int r = row0 + mi * 16;
            float f0 = acc[mi][ni][0] + bz0, f1 = acc[mi][ni][1] + bz1;
            float f2 = acc[mi][ni][2] + bz0, f3 = acc[mi][ni][3] + bz1;
            if (relu_flag) {
                f0 = fmaxf(f0, 0.f); f1 = fmaxf(f1, 0.f);
                f2 = fmaxf(f2, 0.f); f3 = fmaxf(f3, 0.f);
            }
            if (var) {
                f0 = s0 * f0 + sh0; f1 = s1 * f1 + sh1;
                f2 = s0 * f2 + sh0; f3 = s1 * f3 + sh1;
            }
            if (round_out) {
                f0 = rtf32(f0); f1 = rtf32(f1); f2 = rtf32(f2); f3 = rtf32(f3);
            }
            *(float2*)(C + (size_t)r * Nn + c)        = make_float2(f0, f1);
            *(float2*)(C + (size_t)(r + 8) * Nn + c)  = make_float2(f2, f3);
        }
    }
}

// ---------------- aggregation core: MLP-4 unrolled gather ---------------------
template <int D>
__device__ __forceinline__ float4 agg_row(const float4* __restrict__ h4, int n, int t)
{
    const int V = D / 4;
    float din = g_dinv[n];
    float wself = din * din;
    float4 a = h4[(size_t)n * V + t];
    float4 acc0 = make_float4(a.x * wself, a.y * wself, a.z * wself, a.w * wself);
    float4 acc1 = make_float4(0.f, 0.f, 0.f, 0.f);

    int e = g_rowptr[n], end = g_rowptr[n + 1];
    for (; e + 4 <= end; e += 4) {
        int s0 = g_colsrc[e],     s1 = g_colsrc[e + 1];
        int s2 = g_colsrc[e + 2], s3 = g_colsrc[e + 3];
        float w0 = g_normv[e],     w1 = g_normv[e + 1];
        float w2 = g_normv[e + 2], w3 = g_normv[e + 3];
        float4 v0 = h4[(size_t)s0 * V + t];
        float4 v1 = h4[(size_t)s1 * V + t];
        float4 v2 = h4[(size_t)s2 * V + t];
        float4 v3 = h4[(size_t)s3 * V + t];
        acc0.x = fmaf(w0, v0.x, acc0.x); acc0.y = fmaf(w0, v0.y, acc0.y);
        acc0.z = fmaf(w0, v0.z, acc0.z); acc0.w = fmaf(w0, v0.w, acc0.w);
        acc1.x = fmaf(w1, v1.x, acc1.x); acc1.y = fmaf(w1, v1.y, acc1.y);
        acc1.z = fmaf(w1, v1.z, acc1.z); acc1.w = fmaf(w1, v1.w, acc1.w);
        acc0.x = fmaf(w2, v2.x, acc0.x); acc0.y = fmaf(w2, v2.y, acc0.y);
        acc0.z = fmaf(w2, v2.z, acc0.z); acc0.w = fmaf(w2, v2.w, acc0.w);
        acc1.x = fmaf(w3, v3.x, acc1.x); acc1.y = fmaf(w3, v3.y, acc1.y);
        acc1.z = fmaf(w3, v3.z, acc1.z); acc1.w = fmaf(w3, v3.w, acc1.w);
    }
    if (e + 2 <= end) {
        int s0 = g_colsrc[e], s1 = g_colsrc[e + 1];
        float w0 = g_normv[e], w1 = g_normv[e + 1];
        float4 v0 = h4[(size_t)s0 * V + t];
        float4 v1 = h4[(size_t)s1 * V + t];
        acc0.x = fmaf(w0, v0.x, acc0.x); acc0.y = fmaf(w0, v0.y, acc0.y);
        acc0.z = fmaf(w0, v0.z, acc0.z); acc0.w = fmaf(w0, v0.w, acc0.w);
        acc1.x = fmaf(w1, v1.x, acc1.x); acc1.y = fmaf(w1, v1.y, acc1.y);
        acc1.z = fmaf(w1, v1.z, acc1.z); acc1.w = fmaf(w1, v1.w, acc1.w);
        e += 2;
    }
    if (e < end) {
        int s0 = g_colsrc[e];
        float w0 = g_normv[e];
        float4 v0 = h4[(size_t)s0 * V + t];
        acc0.x = fmaf(w0, v0.x, acc0.x); acc0.y = fmaf(w0, v0.y, acc0.y);
        acc0.z = fmaf(w0, v0.z, acc0.z); acc0.w = fmaf(w0, v0.w, acc0.w);
    }
    return make_float4(acc0.x + acc1.x, acc0.y + acc1.y,
                       acc0.z + acc1.z, acc0.w + acc1.w);
}

// plain (feeds a GEMM A operand -> round output to tf32)
template <int D>
__global__ void aggp_kernel(const float* __restrict__ hin, float* __restrict__ hout)
{
    int n = blockIdx.x;
    int t = threadIdx.x;
    float4 r = agg_row<D>((const float4*)hin, n, t);
    ((float4*)hout)[(size_t)n * (D / 4) + t] =
        make_float4(rtf32(r.x), rtf32(r.y), rtf32(r.z), rtf32(r.w));
}

// epilogue version (final layer, feeds pool -> stay fp32): out = bn(relu(agg + b))
template <int D>
__global__ void agg_kernel(const float* __restrict__ hin, float* __restrict__ hout,
                           const float* __restrict__ bias, const float* __restrict__ gam,
                           const float* __restrict__ bet,  const float* __restrict__ mu,
                           const float* __restrict__ var)
{
    int n = blockIdx.x;
    int t = threadIdx.x;
    float4 r = agg_row<D>((const float4*)hin, n, t);

    int c = t * 4;
    float4 b4 = *(const float4*)(bias + c);
    float4 gg = *(const float4*)(gam + c);
    float4 bb = *(const float4*)(bet + c);
    float4 mm = *(const float4*)(mu + c);
    float4 vv = *(const float4*)(var + c);

    float ax = fmaxf(r.x + b4.x, 0.f);
    float ay = fmaxf(r.y + b4.y, 0.f);
    float az = fmaxf(r.z + b4.z, 0.f);
    float aw = fmaxf(r.w + b4.w, 0.f);

    float4 o;
    o.x = gg.x * (ax - mm.x) * rsqrtf(vv.x + BN_EPS) + bb.x;
    o.y = gg.y * (ay - mm.y) * rsqrtf(vv.y + BN_EPS) + bb.y;
    o.z = gg.z * (az - mm.z) * rsqrtf(vv.z + BN_EPS) + bb.z;
    o.w = gg.w * (aw - mm.w) * rsqrtf(vv.w + BN_EPS) + bb.w;
    ((float4*)hout)[(size_t)n * (D / 4) + t] = o;
}

// ---------------- mean pool over sorted batch (rounds output: feeds head GEMM) -
__device__ __forceinline__ int lowerb(const int* __restrict__ b, int n, int v) {
    int lo = 0, hi = n;
    while (lo < hi) {
        int m = (lo + hi) >> 1;
        if (b[m] < v) lo = m + 1; else hi = m;
    }
    return lo;
}

__global__ void pool_kernel(const float* __restrict__ h, const int* __restrict__ batch,
                            float* __restrict__ pooled)
{
    __shared__ int s_lo, s_hi;
    int g = blockIdx.x;
    if (threadIdx.x == 0) {
        s_lo = lowerb(batch, N_NODES, g);
        s_hi = lowerb(batch, N_NODES, g + 1);
    }
    __syncthreads();
    int lo = s_lo, hi = s_hi;
    const float4* h4 = (const float4*)h;
    float4 acc = make_float4(0.f, 0.f, 0.f, 0.f);
    for (int r = lo; r < hi; r++) {
        float4 v = h4[(size_t)r * (DIM_OUT / 4) + threadIdx.x];
        acc.x += v.x; acc.y += v.y; acc.z += v.z; acc.w += v.w;
    }
    float inv = 1.f / fmaxf((float)(hi - lo), 1.f);
    ((float4*)pooled)[g * (DIM_OUT / 4) + threadIdx.x] =
        make_float4(rtf32(acc.x * inv), rtf32(acc.y * inv),
                    rtf32(acc.z * inv), rtf32(acc.w * inv));
}

// ---------------- launch ------------------------------------------------------
extern "C" void kernel_launch(void* const* d_in, const int* in_sizes, int n_in,
                              void* d_out, int out_size)
{
    const float* x   = (const float*)d_in[0];
    const int*   ei  = (const int*)d_in[1];
    const int*   bat = (const int*)d_in[2];
    const float* W1  = (const float*)d_in[3];
    const float* b1  = (const float*)d_in[4];
    const float* W2  = (const float*)d_in[5];
    const float* b2  = (const float*)d_in[6];
    const float* W3  = (const float*)d_in[7];
    const float* b3  = (const float*)d_in[8];
    const float* g1  = (const float*)d_in[9];
    const float* be1 = (const float*)d_in[10];
    const float* m1  = (const float*)d_in[11];
    const float* v1  = (const float*)d_in[12];
    const float* g2  = (const float*)d_in[13];
    const float* be2 = (const float*)d_in[14];
    const float* m2  = (const float*)d_in[15];
    const float* v2  = (const float*)d_in[16];
    const float* g3  = (const float*)d_in[17];
    const float* be3 = (const float*)d_in[18];
    const float* m3  = (const float*)d_in[19];
    const float* v3  = (const float*)d_in[20];
    const float* Wf1 = (const float*)d_in[21];
    const float* bf1 = (const float*)d_in[22];
    const float* Wf2 = (const float*)d_in[23];
    const float* bf2 = (const float*)d_in[24];

    const int* src = ei;
    const int* dst = ei + N_EDGES;

    float *bufA, *bufB, *pooled, *f1, *wr;
    cudaGetSymbolAddress((void**)&bufA,   g_bufA);
    cudaGetSymbolAddress((void**)&bufB,   g_bufB);
    cudaGetSymbolAddress((void**)&pooled, g_pooled);
    cudaGetSymbolAddress((void**)&f1,     g_f1);
    cudaGetSymbolAddress((void**)&wr,     g_wr);

    // ---- graph preprocessing + weight rounding ----
    zero_degc_kernel<<<N_NODES / 256, 256>>>();
    count_kernel<<<N_EDGES / 256, 256>>>(dst);
    scan_p1_kernel<<<128, 1024>>>();
    scan_p2_kernel<<<1, 128>>>();
    scan_p3_kernel<<<N_NODES / 256, 256>>>();
    fill_kernel<<<N_EDGES / 256, 256>>>(src, dst);
    round_w_kernel<<<(NWTOT + 255) / 256, 256>>>(W1, W2, W3, Wf1, Wf2);

    // ---- layer 1: agg(x) [dim 128] -> GEMM 128->512 fused bias+relu+bn ----
    aggp_kernel<DIM_IN><<<N_NODES, DIM_IN / 4>>>(x, bufA);
    {
        dim3 grid(DIM_H / 128, N_NODES / 128);
        tgemm_kernel<<<grid, 256>>>(bufA, wr + OW1, bufB, N_NODES, DIM_H, DIM_IN,
                                    b1, g1, be1, m1, v1, 1, 0);
    }
    // ---- layer 2: agg(h) [512] -> GEMM 512->512 fused epilogue (+round for L3) ----
    aggp_kernel<DIM_H><<<N_NODES, DIM_H / 4>>>(bufB, bufA);
    {
        dim3 grid(DIM_H / 128, N_NODES / 128);
        tgemm_kernel<<<grid, 256>>>(bufA, wr + OW2, bufB, N_NODES, DIM_H, DIM_H,
                                    b2, g2, be2, m2, v2, 1, 1);
    }
    // ---- layer 3: GEMM 512->256 plain -> agg [256] with epilogue ----
    {
        dim3 grid(DIM_OUT / 128, N_NODES / 128);
        tgemm_kernel<<<grid, 256>>>(bufB, wr + OW3, bufA, N_NODES, DIM_OUT, DIM_H,
                                    nullptr, nullptr, nullptr, nullptr, nullptr, 0, 0);
    }
    agg_kernel<DIM_OUT><<<N_NODES, DIM_OUT / 4>>>(bufA, bufB, b3, g3, be3, m3, v3);

    // ---- mean pool (rounds output for head GEMM) ----
    pool_kernel<<<N_GRAPHS, DIM_OUT / 4>>>(bufB, bat, pooled);

    // ---- MLP head ----
    {
        dim3 grid(DIM_OUT / 128, N_GRAPHS / 128);
        tgemm_kernel<<<grid, 256>>>(pooled, wr + OWF1, f1, N_GRAPHS, DIM_OUT, DIM_OUT,
                                    bf1, nullptr, nullptr, nullptr, nullptr, 1, 1);
        tgemm_kernel<<<grid, 256>>>(f1, wr + OWF2, (float*)d_out, N_GRAPHS, DIM_OUT, DIM_OUT,
                                    bf2, nullptr, nullptr, nullptr, nullptr, 0, 0);
    }
}

// round 12
// speedup vs baseline: 2.3345x; 1.0009x over previous
#include <cuda_runtime.h>
#include <cstdint>

#define N_NODES 131072
#define N_EDGES 524288
#define N_GRAPHS 4096
#define DIM_IN 128
#define DIM_H 512
#define DIM_OUT 256
#define BN_EPS 1e-5f

// ---------------- scratch (device globals; no allocation allowed) -------------
__device__ float g_bufA[(size_t)N_NODES * DIM_H];
__device__ float g_bufB[(size_t)N_NODES * DIM_H];
__device__ float g_pooled[N_GRAPHS * DIM_OUT];
__device__ float g_f1[N_GRAPHS * DIM_OUT];
__device__ float g_wr[589824];          // tf32-rounded weights, concatenated
__device__ int   g_degc[N_NODES];
__device__ int   g_rowptr[N_NODES + 1];
__device__ int   g_cursor[N_NODES];
__device__ int   g_colsrc[N_EDGES];
__device__ float g_normv[N_EDGES];
__device__ float g_dinv[N_NODES];
__device__ int   g_blksum[128];
__device__ int   g_blkoff[128];

// weight offsets in g_wr
#define OW1  0
#define OW2  65536
#define OW3  327680
#define OWF1 458752
#define OWF2 524288
#define NWTOT 589824

__device__ __forceinline__ uint32_t f2tf32(float f) {
    uint32_t r;
    asm("cvt.rna.tf32.f32 %0, %1;" : "=r"(r) : "f"(f));
    return r;
}
__device__ __forceinline__ float rtf32(float f) { return __uint_as_float(f2tf32(f)); }

// ---------------- graph preprocessing ----------------------------------------
__global__ void zero_degc_kernel() {
    int i = blockIdx.x * blockDim.x + threadIdx.x;
    if (i < N_NODES) g_degc[i] = 0;
}

__global__ void count_kernel(const int* __restrict__ dst) {
    int e = blockIdx.x * blockDim.x + threadIdx.x;
    if (e < N_EDGES) atomicAdd(&g_degc[dst[e]], 1);
}

__global__ void scan_p1_kernel() {
    __shared__ int s[1024];
    int i = blockIdx.x * 1024 + threadIdx.x;
    int v = g_degc[i];
    s[threadIdx.x] = v;
    __syncthreads();
    for (int off = 1; off < 1024; off <<= 1) {
        int t = (threadIdx.x >= off) ? s[threadIdx.x - off] : 0;
        __syncthreads();
        s[threadIdx.x] += t;
        __syncthreads();
    }
    g_cursor[i] = s[threadIdx.x];
    if (threadIdx.x == 1023) g_blksum[blockIdx.x] = s[1023];
}

__global__ void scan_p2_kernel() {
    __shared__ int s[128];
    int t = threadIdx.x;
    s[t] = g_blksum[t];
    __syncthreads();
    for (int off = 1; off < 128; off <<= 1) {
        int v = (t >= off) ? s[t - off] : 0;
        __syncthreads();
        s[t] += v;
        __syncthreads();
    }
    g_blkoff[t] = (t == 0) ? 0 : s[t - 1];
}

__global__ void scan_p3_kernel() {   // also computes dinv
    int i = blockIdx.x * blockDim.x + threadIdx.x;
    if (i < N_NODES) {
        int d = g_degc[i];
        int excl = g_cursor[i] - d + g_blkoff[i >> 10];
        g_rowptr[i] = excl;
        g_cursor[i] = excl;
        g_dinv[i] = rsqrtf((float)(d + 1));
        if (i == N_NODES - 1) g_rowptr[N_NODES] = excl + d;
    }
}

__global__ void fill_kernel(const int* __restrict__ src, const int* __restrict__ dst) {
    int e = blockIdx.x * blockDim.x + threadIdx.x;
    if (e < N_EDGES) {
        int s = src[e], d = dst[e];
        int p = atomicAdd(&g_cursor[d], 1);
        g_colsrc[p] = s;
        g_normv[p]  = g_dinv[s] * g_dinv[d];
    }
}

// ---------------- weight rounding (tf32 RNA, one pass) ------------------------
__global__ void round_w_kernel(const float* __restrict__ W1, const float* __restrict__ W2,
                               const float* __restrict__ W3, const float* __restrict__ Wf1,
                               const float* __restrict__ Wf2)
{
    int i = blockIdx.x * blockDim.x + threadIdx.x;
    if (i >= NWTOT) return;
    float v;
    if      (i < OW2)  v = W1[i - OW1];
    else if (i < OW3)  v = W2[i - OW2];
    else if (i < OWF1) v = W3[i - OW3];
    else if (i < OWF2) v = Wf1[i - OWF1];
    else               v = Wf2[i - OWF2];
    g_wr[i] = rtf32(v);
}

// ---------------- TF32 tensor-core GEMM, 3-stage cp.async pipeline ------------
// C[M,Nn] = A[M,K] @ B[K,Nn]; A,B must be tf32-pre-rounded fp32.
#define MMA_TF32(d, a, b0, b1)                                                   \
    asm volatile("mma.sync.aligned.m16n8k8.row.col.f32.tf32.tf32.f32 "          \
        "{%0,%1,%2,%3}, {%4,%5,%6,%7}, {%8,%9}, {%0,%1,%2,%3};"                 \
        : "+f"(d[0]), "+f"(d[1]), "+f"(d[2]), "+f"(d[3])                        \
        : "r"(a[0]), "r"(a[1]), "r"(a[2]), "r"(a[3]), "r"(b0), "r"(b1))

__device__ __forceinline__ void cpa16(uint32_t dst, const float* src) {
    asm volatile("cp.async.ca.shared.global [%0], [%1], 16;" :: "r"(dst), "l"(src));
}

__global__ __launch_bounds__(256, 2) void tgemm_kernel(
    const float* __restrict__ A, const float* __restrict__ B, float* __restrict__ C,
    int M, int Nn, int K,
    const float* __restrict__ bias, const float* __restrict__ gam,
    const float* __restrict__ bet,  const float* __restrict__ mu,
    const float* __restrict__ var,  int relu_flag, int round_out)
{
    const int BM = 128, BN = 128, BK = 16;
    const int ASTR = 20, BSTR = 132;                // bank-tuned strides
    __shared__ float As[3][BM * ASTR];              // [m][k]
    __shared__ float Bs[3][BK * BSTR];              // [k][n]

    int tid  = threadIdx.x;
    int lane = tid & 31, warp = tid >> 5;
    int wm = warp & 3, wn = warp >> 2;              // 4 x 2 warp grid
    int gid = lane >> 2, tig = lane & 3;

    const float* Ab = A + (size_t)blockIdx.y * BM * K;
    const float* Bb = B + (size_t)blockIdx.x * BN;

    int a_row[2], a_col[2], b_row[2], b_col[2];
    uint32_t a_sm[2], b_sm[2];
#pragma unroll
    for (int i = 0; i < 2; i++) {
        int s = tid + i * 256;                      // 512 float4 slots per tile
        a_row[i] = s >> 2;  a_col[i] = (s & 3) * 4;     // A: 128 x 16
        b_row[i] = s >> 5;  b_col[i] = (s & 31) * 4;    // B: 16 x 128
        a_sm[i] = (uint32_t)__cvta_generic_to_shared(&As[0][a_row[i] * ASTR + a_col[i]]);
        b_sm[i] = (uint32_t)__cvta_generic_to_shared(&Bs[0][b_row[i] * BSTR + b_col[i]]);
    }
    const uint32_t aStageB = (uint32_t)(BM * ASTR * 4);
    const uint32_t bStageB = (uint32_t)(BK * BSTR * 4);

    float acc[2][8][4];
#pragma unroll
    for (int mi = 0; mi < 2; mi++)
#pragma unroll
        for (int ni = 0; ni < 8; ni++)
#pragma unroll
            for (int j = 0; j < 4; j++) acc[mi][ni][j] = 0.f;

    int nIter = K / BK;
    // prologue: stages 0 and 1
#pragma unroll
    for (int st = 0; st < 2; st++) {
        int k0 = st * BK;
#pragma unroll
        for (int i = 0; i < 2; i++) {
            cpa16(a_sm[i] + st * aStageB, Ab + (size_t)a_row[i] * K + k0 + a_col[i]);
            cpa16(b_sm[i] + st * bStageB, Bb + (size_t)(k0 + b_row[i]) * Nn + b_col[i]);
        }
        asm volatile("cp.async.commit_group;");
    }

    for (int it = 0; it < nIter; it++) {
        int stg = it % 3;
        asm volatile("cp.async.wait_group 1;");
        __syncthreads();

        const float* Asb = As[stg];
        const float* Bsb = Bs[stg];
#pragma unroll
        for (int ks = 0; ks < BK; ks += 8) {
            // ---- batch-load ALL fragments for this ks-half first ----
            uint32_t af[2][4];
            uint32_t bf[8][2];
#pragma unroll
            for (int mi = 0; mi < 2; mi++) {
                int rb = wm * 32 + mi * 16;
                af[mi][0] = __float_as_uint(Asb[(rb + gid)     * ASTR + ks + tig]);
                af[mi][1] = __float_as_uint(Asb[(rb + gid + 8) * ASTR + ks + tig]);
                af[mi][2] = __float_as_uint(Asb[(rb + gid)     * ASTR + ks + tig + 4]);
                af[mi][3] = __float_as_uint(Asb[(rb + gid + 8) * ASTR + ks + tig + 4]);
            }
#pragma unroll
            for (int ni = 0; ni < 8; ni++) {
                int nb = wn * 64 + ni * 8;
                bf[ni][0] = __float_as_uint(Bsb[(ks + tig)     * BSTR + nb + gid]);
                bf[ni][1] = __float_as_uint(Bsb[(ks + tig + 4) * BSTR + nb + gid]);
            }
            // ---- then issue all 16 MMAs back-to-back ----
#pragma unroll
            for (int ni = 0; ni < 8; ni++) {
                MMA_TF32(acc[0][ni], af[0], bf[ni][0], bf[ni][1]);
                MMA_TF32(acc[1][ni], af[1], bf[ni][0], bf[ni][1]);
            }
        }

        // issue stage it+2 AFTER compute: previous-iteration sync guards WAR
        if (it + 2 < nIter) {
            int k0 = (it + 2) * BK;
            uint32_t so = (uint32_t)((it + 2) % 3);
#pragma unroll
            for (int i = 0; i < 2; i++) {
                cpa16(a_sm[i] + so * aStageB, Ab + (size_t)a_row[i] * K + k0 + a_col[i]);
                cpa16(b_sm[i] + so * bStageB, Bb + (size_t)(k0 + b_row[i]) * Nn + b_col[i]);
            }
        }
        asm volatile("cp.async.commit_group;");
    }

    // epilogue
    int row0 = blockIdx.y * BM + wm * 32 + gid;
#pragma unroll
    for (int ni = 0; ni < 8; ni++) {
        int c = blockIdx.x * BN + wn * 64 + ni * 8 + 2 * tig;
        float bz0 = 0.f, bz1 = 0.f, s0 = 1.f, s1 = 1.f, sh0 = 0.f, sh1 = 0.f;
        if (bias) { float2 b2 = *(const float2*)(bias + c); bz0 = b2.x; bz1 = b2.y; }
        if (var) {
            float2 gg = *(const float2*)(gam + c);
            float2 vv = *(const float2*)(var + c);
            float2 mm = *(const float2*)(mu  + c);
            float2 bb = *(const float2*)(bet + c);
            s0 = gg.x * rsqrtf(vv.x + BN_EPS);  s1 = gg.y * rsqrtf(vv.y + BN_EPS);
            sh0 = bb.x - s0 * mm.x;             sh1 = bb.y - s1 * mm.y;
        }
#pragma unroll
        for (int mi = 0; mi < 2; mi++) {
            int r = row0 + mi * 16;
            float f0 = acc[mi][ni][0] + bz0, f1 = acc[mi][ni][1] + bz1;
            float f2 = acc[mi][ni][2] + bz0, f3 = acc[mi][ni][3] + bz1;
            if (relu_flag) {
                f0 = fmaxf(f0, 0.f); f1 = fmaxf(f1, 0.f);
                f2 = fmaxf(f2, 0.f); f3 = fmaxf(f3, 0.f);
            }
            if (var) {
                f0 = s0 * f0 + sh0; f1 = s1 * f1 + sh1;
                f2 = s0 * f2 + sh0; f3 = s1 * f3 + sh1;
            }
            if (round_out) {
                f0 = rtf32(f0); f1 = rtf32(f1); f2 = rtf32(f2); f3 = rtf32(f3);
            }
            *(float2*)(C + (size_t)r * Nn + c)        = make_float2(f0, f1);
            *(float2*)(C + (size_t)(r + 8) * Nn + c)  = make_float2(f2, f3);
        }
    }
}

// ---------------- aggregation core: MLP-4 unrolled gather ---------------------
template <int D>
__device__ __forceinline__ float4 agg_row(const float4* __restrict__ h4, int n, int t)
{
    const int V = D / 4;
    float din = g_dinv[n];
    float wself = din * din;
    float4 a = h4[(size_t)n * V + t];
    float4 acc0 = make_float4(a.x * wself, a.y * wself, a.z * wself, a.w * wself);
    float4 acc1 = make_float4(0.f, 0.f, 0.f, 0.f);

    int e = g_rowptr[n], end = g_rowptr[n + 1];
    for (; e + 4 <= end; e += 4) {
        int s0 = g_colsrc[e],     s1 = g_colsrc[e + 1];
        int s2 = g_colsrc[e + 2], s3 = g_colsrc[e + 3];
        float w0 = g_normv[e],     w1 = g_normv[e + 1];
        float w2 = g_normv[e + 2], w3 = g_normv[e + 3];
        float4 v0 = h4[(size_t)s0 * V + t];
        float4 v1 = h4[(size_t)s1 * V + t];
        float4 v2 = h4[(size_t)s2 * V + t];
        float4 v3 = h4[(size_t)s3 * V + t];
        acc0.x = fmaf(w0, v0.x, acc0.x); acc0.y = fmaf(w0, v0.y, acc0.y);
        acc0.z = fmaf(w0, v0.z, acc0.z); acc0.w = fmaf(w0, v0.w, acc0.w);
        acc1.x = fmaf(w1, v1.x, acc1.x); acc1.y = fmaf(w1, v1.y, acc1.y);
        acc1.z = fmaf(w1, v1.z, acc1.z); acc1.w = fmaf(w1, v1.w, acc1.w);
        acc0.x = fmaf(w2, v2.x, acc0.x); acc0.y = fmaf(w2, v2.y, acc0.y);
        acc0.z = fmaf(w2, v2.z, acc0.z); acc0.w = fmaf(w2, v2.w, acc0.w);
        acc1.x = fmaf(w3, v3.x, acc1.x); acc1.y = fmaf(w3, v3.y, acc1.y);
        acc1.z = fmaf(w3, v3.z, acc1.z); acc1.w = fmaf(w3, v3.w, acc1.w);
    }
    if (e + 2 <= end) {
        int s0 = g_colsrc[e], s1 = g_colsrc[e + 1];
        float w0 = g_normv[e], w1 = g_normv[e + 1];
        float4 v0 = h4[(size_t)s0 * V + t];
        float4 v1 = h4[(size_t)s1 * V + t];
        acc0.x = fmaf(w0, v0.x, acc0.x); acc0.y = fmaf(w0, v0.y, acc0.y);
        acc0.z = fmaf(w0, v0.z, acc0.z); acc0.w = fmaf(w0, v0.w, acc0.w);
        acc1.x = fmaf(w1, v1.x, acc1.x); acc1.y = fmaf(w1, v1.y, acc1.y);
        acc1.z = fmaf(w1, v1.z, acc1.z); acc1.w = fmaf(w1, v1.w, acc1.w);
        e += 2;
    }
    if (e < end) {
        int s0 = g_colsrc[e];
        float w0 = g_normv[e];
        float4 v0 = h4[(size_t)s0 * V + t];
        acc0.x = fmaf(w0, v0.x, acc0.x); acc0.y = fmaf(w0, v0.y, acc0.y);
        acc0.z = fmaf(w0, v0.z, acc0.z); acc0.w = fmaf(w0, v0.w, acc0.w);
    }
    return make_float4(acc0.x + acc1.x, acc0.y + acc1.y,
                       acc0.z + acc1.z, acc0.w + acc1.w);
}

// plain (feeds a GEMM A operand -> round output to tf32)
template <int D>
__global__ void aggp_kernel(const float* __restrict__ hin, float* __restrict__ hout)
{
    int n = blockIdx.x;
    int t = threadIdx.x;
    float4 r = agg_row<D>((const float4*)hin, n, t);
    ((float4*)hout)[(size_t)n * (D / 4) + t] =
        make_float4(rtf32(r.x), rtf32(r.y), rtf32(r.z), rtf32(r.w));
}

// epilogue version (final layer, feeds pool -> stay fp32): out = bn(relu(agg + b))
template <int D>
__global__ void agg_kernel(const float* __restrict__ hin, float* __restrict__ hout,
                           const float* __restrict__ bias, const float* __restrict__ gam,
                           const float* __restrict__ bet,  const float* __restrict__ mu,
                           const float* __restrict__ var)
{
    int n = blockIdx.x;
    int t = threadIdx.x;
    float4 r = agg_row<D>((const float4*)hin, n, t);

    int c = t * 4;
    float4 b4 = *(const float4*)(bias + c);
    float4 gg = *(const float4*)(gam + c);
    float4 bb = *(const float4*)(bet + c);
    float4 mm = *(const float4*)(mu + c);
    float4 vv = *(const float4*)(var + c);

    float ax = fmaxf(r.x + b4.x, 0.f);
    float ay = fmaxf(r.y + b4.y, 0.f);
    float az = fmaxf(r.z + b4.z, 0.f);
    float aw = fmaxf(r.w + b4.w, 0.f);

    float4 o;
    o.x = gg.x * (ax - mm.x) * rsqrtf(vv.x + BN_EPS) + bb.x;
    o.y = gg.y * (ay - mm.y) * rsqrtf(vv.y + BN_EPS) + bb.y;
    o.z = gg.z * (az - mm.z) * rsqrtf(vv.z + BN_EPS) + bb.z;
    o.w = gg.w * (aw - mm.w) * rsqrtf(vv.w + BN_EPS) + bb.w;
    ((float4*)hout)[(size_t)n * (D / 4) + t] = o;
}

// ---------------- mean pool over sorted batch (rounds output: feeds head GEMM) -
__device__ __forceinline__ int lowerb(const int* __restrict__ b, int n, int v) {
    int lo = 0, hi = n;
    while (lo < hi) {
        int m = (lo + hi) >> 1;
        if (b[m] < v) lo = m + 1; else hi = m;
    }
    return lo;
}

__global__ void pool_kernel(const float* __restrict__ h, const int* __restrict__ batch,
                            float* __restrict__ pooled)
{
    __shared__ int s_lo, s_hi;
    int g = blockIdx.x;
    if (threadIdx.x == 0) {
        s_lo = lowerb(batch, N_NODES, g);
        s_hi = lowerb(batch, N_NODES, g + 1);
    }
    __syncthreads();
    int lo = s_lo, hi = s_hi;
    const float4* h4 = (const float4*)h;
    float4 acc = make_float4(0.f, 0.f, 0.f, 0.f);
    for (int r = lo; r < hi; r++) {
        float4 v = h4[(size_t)r * (DIM_OUT / 4) + threadIdx.x];
        acc.x += v.x; acc.y += v.y; acc.z += v.z; acc.w += v.w;
    }
    float inv = 1.f / fmaxf((float)(hi - lo), 1.f);
    ((float4*)pooled)[g * (DIM_OUT / 4) + threadIdx.x] =
        make_float4(rtf32(acc.x * inv), rtf32(acc.y * inv),
                    rtf32(acc.z * inv), rtf32(acc.w * inv));
}

// ---------------- launch ------------------------------------------------------
extern "C" void kernel_launch(void* const* d_in, const int* in_sizes, int n_in,
                              void* d_out, int out_size)
{
    const float* x   = (const float*)d_in[0];
    const int*   ei  = (const int*)d_in[1];
    const int*   bat = (const int*)d_in[2];
    const float* W1  = (const float*)d_in[3];
    const float* b1  = (const float*)d_in[4];
    const float* W2  = (const float*)d_in[5];
    const float* b2  = (const float*)d_in[6];
    const float* W3  = (const float*)d_in[7];
    const float* b3  = (const float*)d_in[8];
    const float* g1  = (const float*)d_in[9];
    const float* be1 = (const float*)d_in[10];
    const float* m1  = (const float*)d_in[11];
    const float* v1  = (const float*)d_in[12];
    const float* g2  = (const float*)d_in[13];
    const float* be2 = (const float*)d_in[14];
    const float* m2  = (const float*)d_in[15];
    const float* v2  = (const float*)d_in[16];
    const float* g3  = (const float*)d_in[17];
    const float* be3 = (const float*)d_in[18];
    const float* m3  = (const float*)d_in[19];
    const float* v3  = (const float*)d_in[20];
    const float* Wf1 = (const float*)d_in[21];
    const float* bf1 = (const float*)d_in[22];
    const float* Wf2 = (const float*)d_in[23];
    const float* bf2 = (const float*)d_in[24];

    const int* src = ei;
    const int* dst = ei + N_EDGES;

    float *bufA, *bufB, *pooled, *f1, *wr;
    cudaGetSymbolAddress((void**)&bufA,   g_bufA);
    cudaGetSymbolAddress((void**)&bufB,   g_bufB);
    cudaGetSymbolAddress((void**)&pooled, g_pooled);
    cudaGetSymbolAddress((void**)&f1,     g_f1);
    cudaGetSymbolAddress((void**)&wr,     g_wr);

    // ---- graph preprocessing + weight rounding ----
    zero_degc_kernel<<<N_NODES / 256, 256>>>();
    count_kernel<<<N_EDGES / 256, 256>>>(dst);
    scan_p1_kernel<<<128, 1024>>>();
    scan_p2_kernel<<<1, 128>>>();
    scan_p3_kernel<<<N_NODES / 256, 256>>>();
    fill_kernel<<<N_EDGES / 256, 256>>>(src, dst);
    round_w_kernel<<<(NWTOT + 255) / 256, 256>>>(W1, W2, W3, Wf1, Wf2);

    // ---- layer 1: agg(x) [dim 128] -> GEMM 128->512 fused bias+relu+bn ----
    aggp_kernel<DIM_IN><<<N_NODES, DIM_IN / 4>>>(x, bufA);
    {
        dim3 grid(DIM_H / 128, N_NODES / 128);
        tgemm_kernel<<<grid, 256>>>(bufA, wr + OW1, bufB, N_NODES, DIM_H, DIM_IN,
                                    b1, g1, be1, m1, v1, 1, 0);
    }
    // ---- layer 2: agg(h) [512] -> GEMM 512->512 fused epilogue (+round for L3) ----
    aggp_kernel<DIM_H><<<N_NODES, DIM_H / 4>>>(bufB, bufA);
    {
        dim3 grid(DIM_H / 128, N_NODES / 128);
        tgemm_kernel<<<grid, 256>>>(bufA, wr + OW2, bufB, N_NODES, DIM_H, DIM_H,
                                    b2, g2, be2, m2, v2, 1, 1);
    }
    // ---- layer 3: GEMM 512->256 plain -> agg [256] with epilogue ----
    {
        dim3 grid(DIM_OUT / 128, N_NODES / 128);
        tgemm_kernel<<<grid, 256>>>(bufB, wr + OW3, bufA, N_NODES, DIM_OUT, DIM_H,
                                    nullptr, nullptr, nullptr, nullptr, nullptr, 0, 0);
    }
    agg_kernel<DIM_OUT><<<N_NODES, DIM_OUT / 4>>>(bufA, bufB, b3, g3, be3, m3, v3);

    // ---- mean pool (rounds output for head GEMM) ----
    pool_kernel<<<N_GRAPHS, DIM_OUT / 4>>>(bufB, bat, pooled);

    // ---- MLP head ----
    {
        dim3 grid(DIM_OUT / 128, N_GRAPHS / 128);
        tgemm_kernel<<<grid, 256>>>(pooled, wr + OWF1, f1, N_GRAPHS, DIM_OUT, DIM_OUT,
                                    bf1, nullptr, nullptr, nullptr, nullptr, 1, 1);
        tgemm_kernel<<<grid, 256>>>(f1, wr + OWF2, (float*)d_out, N_GRAPHS, DIM_OUT, DIM_OUT,
                                    bf2, nullptr, nullptr, nullptr, nullptr, 0, 0);
    }
}

// round 17
// speedup vs baseline: 2.8656x; 1.2275x over previous
#include <cuda_runtime.h>
#include <cuda_fp16.h>
#include <cstdint>

#define N_NODES 131072
#define N_EDGES 524288
#define N_GRAPHS 4096
#define DIM_IN 128
#define DIM_H 512
#define DIM_OUT 256
#define BN_EPS 1e-5f

// ---------------- scratch (device globals; no allocation allowed) -------------
__device__ float g_bufA[(size_t)N_NODES * DIM_H];   // reinterpreted as __half
__device__ float g_bufB[(size_t)N_NODES * DIM_H];
__device__ float g_pooled[N_GRAPHS * DIM_OUT];
__device__ float g_f1[N_GRAPHS * DIM_OUT];
__device__ float g_wr[589824];          // holds fp16 TRANSPOSED weights [N,K]
__device__ int   g_degc[N_NODES];
__device__ int   g_rowptr[N_NODES + 1];
__device__ int   g_cursor[N_NODES];
__device__ int   g_colsrc[N_EDGES];
__device__ float g_normv[N_EDGES];
__device__ float g_dinv[N_NODES];
__device__ int   g_blksum[128];
__device__ int   g_blkoff[128];

// weight offsets (element counts, transposed [out,in])
#define OW1  0
#define OW2  65536
#define OW3  327680
#define OWF1 458752
#define OWF2 524288
#define NWTOT 589824

// ---------------- graph preprocessing ----------------------------------------
__global__ void zero_degc_kernel() {
    int i = blockIdx.x * blockDim.x + threadIdx.x;
    if (i < N_NODES) g_degc[i] = 0;
}

__global__ void count_kernel(const int* __restrict__ dst) {
    int e = blockIdx.x * blockDim.x + threadIdx.x;
    if (e < N_EDGES) atomicAdd(&g_degc[dst[e]], 1);
}

__global__ void scan_p1_kernel() {
    __shared__ int s[1024];
    int i = blockIdx.x * 1024 + threadIdx.x;
    int v = g_degc[i];
    s[threadIdx.x] = v;
    __syncthreads();
    for (int off = 1; off < 1024; off <<= 1) {
        int t = (threadIdx.x >= off) ? s[threadIdx.x - off] : 0;
        __syncthreads();
        s[threadIdx.x] += t;
        __syncthreads();
    }
    g_cursor[i] = s[threadIdx.x];
    if (threadIdx.x == 1023) g_blksum[blockIdx.x] = s[1023];
}

__global__ void scan_p2_kernel() {
    __shared__ int s[128];
    int t = threadIdx.x;
    s[t] = g_blksum[t];
    __syncthreads();
    for (int off = 1; off < 128; off <<= 1) {
        int v = (t >= off) ? s[t - off] : 0;
        __syncthreads();
        s[t] += v;
        __syncthreads();
    }
    g_blkoff[t] = (t == 0) ? 0 : s[t - 1];
}

__global__ void scan_p3_kernel() {   // also computes dinv
    int i = blockIdx.x * blockDim.x + threadIdx.x;
    if (i < N_NODES) {
        int d = g_degc[i];
        int excl = g_cursor[i] - d + g_blkoff[i >> 10];
        g_rowptr[i] = excl;
        g_cursor[i] = excl;
        g_dinv[i] = rsqrtf((float)(d + 1));
        if (i == N_NODES - 1) g_rowptr[N_NODES] = excl + d;
    }
}

__global__ void fill_kernel(const int* __restrict__ src, const int* __restrict__ dst) {
    int e = blockIdx.x * blockDim.x + threadIdx.x;
    if (e < N_EDGES) {
        int s = src[e], d = dst[e];
        int p = atomicAdd(&g_cursor[d], 1);
        g_colsrc[p] = s;
        g_normv[p]  = g_dinv[s] * g_dinv[d];
    }
}

// ---------------- weight transpose + fp16 conversion --------------------------
// wh[off + n*Kd + k] = half(W[k*Nd + n])
__global__ void round_w_kernel(const float* __restrict__ W1, const float* __restrict__ W2,
                               const float* __restrict__ W3, const float* __restrict__ Wf1,
                               const float* __restrict__ Wf2)
{
    int i = blockIdx.x * blockDim.x + threadIdx.x;
    if (i >= NWTOT) return;
    const float* W; int off, Kd, Nd;
    if      (i < OW2)  { W = W1;  off = OW1;  Kd = 128; Nd = 512; }
    else if (i < OW3)  { W = W2;  off = OW2;  Kd = 512; Nd = 512; }
    else if (i < OWF1) { W = W3;  off = OW3;  Kd = 512; Nd = 256; }
    else if (i < OWF2) { W = Wf1; off = OWF1; Kd = 256; Nd = 256; }
    else               { W = Wf2; off = OWF2; Kd = 256; Nd = 256; }
    int local = i - off;
    int n = local / Kd, k = local % Kd;
    ((__half*)g_wr)[i] = __float2half_rn(W[(size_t)k * Nd + n]);
}

// ---------------- FP16 tensor-core GEMM, 3-stage cp.async pipeline ------------
// C[M,Nn] = A[M,K] @ Bt^T; A [M,K] half, Bt [Nn,K] half (both K-major).
#define MMA_F16(d, a, b)                                                         \
    asm volatile("mma.sync.aligned.m16n8k16.row.col.f32.f16.f16.f32 "           \
        "{%0,%1,%2,%3}, {%4,%5,%6,%7}, {%8,%9}, {%0,%1,%2,%3};"                 \
        : "+f"(d[0]), "+f"(d[1]), "+f"(d[2]), "+f"(d[3])                        \
        : "r"(a[0]), "r"(a[1]), "r"(a[2]), "r"(a[3]), "r"(b[0]), "r"(b[1]))

__device__ __forceinline__ void cpa16(uint32_t dst, const void* src) {
    asm volatile("cp.async.ca.shared.global [%0], [%1], 16;" :: "r"(dst), "l"(src));
}

#define BKH 32      // K halves per stage
#define HSTR 40     // halves per smem row (bank-conflict-free: stride 20 words)

__global__ __launch_bounds__(256, 2) void hgemm_kernel(
    const __half* __restrict__ A, const __half* __restrict__ Bt, void* __restrict__ Cv,
    int M, int Nn, int K,
    const float* __restrict__ bias, const float* __restrict__ gam,
    const float* __restrict__ bet,  const float* __restrict__ mu,
    const float* __restrict__ var,  int relu_flag, int c_fp32)
{
    __shared__ __half As[3][128 * HSTR];
    __shared__ __half Bs[3][128 * HSTR];

    int tid  = threadIdx.x;
    int lane = tid & 31, warp = tid >> 5;
    int wm = warp & 3, wn = warp >> 2;              // 4 x 2 warp grid, 32x64 tiles
    int gid = lane >> 2, tig = lane & 3;

    const __half* Ab = A  + (size_t)blockIdx.y * 128 * K;
    const __half* Bb = Bt + (size_t)blockIdx.x * 128 * K;

    // cp.async slots: per stage 128 rows x 32 halves = 512 x 16B; 2 slots/thread
    int row_[2], seg_[2];
    uint32_t a_sm[2], b_sm[2];
#pragma unroll
    for (int j = 0; j < 2; j++) {
        int s = tid + j * 256;
        row_[j] = s >> 2;
        seg_[j] = (s & 3) * 8;                      // halves
        a_sm[j] = (uint32_t)__cvta_generic_to_shared(&As[0][row_[j] * HSTR + seg_[j]]);
        b_sm[j] = (uint32_t)__cvta_generic_to_shared(&Bs[0][row_[j] * HSTR + seg_[j]]);
    }
    const uint32_t stageBytes = 128u * HSTR * 2u;

    float acc[2][8][4];
#pragma unroll
    for (int mi = 0; mi < 2; mi++)
#pragma unroll
        for (int ni = 0; ni < 8; ni++)
#pragma unroll
            for (int j = 0; j < 4; j++) acc[mi][ni][j] = 0.f;

    int nIter = K / BKH;
    // prologue: stages 0,1
#pragma unroll
    for (int st = 0; st < 2; st++) {
        int k0 = st * BKH;
#pragma unroll
        for (int j = 0; j < 2; j++) {
            cpa16(a_sm[j] + st * stageBytes, Ab + (size_t)row_[j] * K + k0 + seg_[j]);
            cpa16(b_sm[j] + st * stageBytes, Bb + (size_t)row_[j] * K + k0 + seg_[j]);
        }
        asm volatile("cp.async.commit_group;");
    }

    for (int it = 0; it < nIter; it++) {
        int stg = it % 3;
        asm volatile("cp.async.wait_group 1;");
        __syncthreads();

        const __half* Asb = As[stg];
        const __half* Bsb = Bs[stg];
#pragma unroll
        for (int ks = 0; ks < 2; ks++) {
            int ko = ks * 16 + 2 * tig;
            uint32_t af[2][4], bf[8][2];
#pragma unroll
            for (int mi = 0; mi < 2; mi++) {
                int rb = (wm * 32 + mi * 16 + gid) * HSTR + ko;
                af[mi][0] = *(const uint32_t*)&Asb[rb];
                af[mi][1] = *(const uint32_t*)&Asb[rb + 8 * HSTR];
                af[mi][2] = *(const uint32_t*)&Asb[rb + 8];
                af[mi][3] = *(const uint32_t*)&Asb[rb + 8 * HSTR + 8];
            }
#pragma unroll
            for (int ni = 0; ni < 8; ni++) {
                int nb = (wn * 64 + ni * 8 + gid) * HSTR + ko;
                bf[ni][0] = *(const uint32_t*)&Bsb[nb];
                bf[ni][1] = *(const uint32_t*)&Bsb[nb + 8];
            }
#pragma unroll
            for (int ni = 0; ni < 8; ni++) {
                MMA_F16(acc[0][ni], af[0], bf[ni]);
                MMA_F16(acc[1][ni], af[1], bf[ni]);
            }
        }

        // issue stage it+2 AFTER compute (sync at this iter guards WAR)
        if (it + 2 < nIter) {
            int k0 = (it + 2) * BKH;
            uint32_t so = (uint32_t)((it + 2) % 3);
#pragma unroll
            for (int j = 0; j < 2; j++) {
                cpa16(a_sm[j] + so * stageBytes, Ab + (size_t)row_[j] * K + k0 + seg_[j]);
                cpa16(b_sm[j] + so * stageBytes, Bb + (size_t)row_[j] * K + k0 + seg_[j]);
            }
        }
        asm volatile("cp.async.commit_group;");
    }

    // epilogue
    int row0 = blockIdx.y * 128 + wm * 32 + gid;
#pragma unroll
    for (int ni = 0; ni < 8; ni++) {
        int c = blockIdx.x * 128 + wn * 64 + ni * 8 + 2 * tig;
        float bz0 = 0.f, bz1 = 0.f, s0 = 1.f, s1 = 1.f, sh0 = 0.f, sh1 = 0.f;
        int usebn = (var != nullptr);
        if (bias) { float2 b2 = *(const float2*)(bias + c); bz0 = b2.x; bz1 = b2.y; }
        if (usebn) {
            float2 gg = *(const float2*)(gam + c);
            float2 vv = *(const float2*)(var + c);
            float2 mm = *(const float2*)(mu  + c);
            float2 bb = *(const float2*)(bet + c);
            s0 = gg.x * rsqrtf(vv.x + BN_EPS);  s1 = gg.y * rsqrtf(vv.y + BN_EPS);
            sh0 = bb.x - s0 * mm.x;             sh1 = bb.y - s1 * mm.y;
        }
#pragma unroll
        for (int mi = 0; mi < 2; mi++) {
            int r = row0 + mi * 16;
            float f0 = acc[mi][ni][0] + bz0, f1 = acc[mi][ni][1] + bz1;
            float f2 = acc[mi][ni][2] + bz0, f3 = acc[mi][ni][3] + bz1;
            if (relu_flag) {
                f0 = fmaxf(f0, 0.f); f1 = fmaxf(f1, 0.f);
                f2 = fmaxf(f2, 0.f); f3 = fmaxf(f3, 0.f);
            }
            if (usebn) {
                f0 = s0 * f0 + sh0; f1 = s1 * f1 + sh1;
                f2 = s0 * f2 + sh0; f3 = s1 * f3 + sh1;
            }
            if (c_fp32) {
                float* C = (float*)Cv;
                *(float2*)(C + (size_t)r * Nn + c)       = make_float2(f0, f1);
                *(float2*)(C + (size_t)(r + 8) * Nn + c) = make_float2(f2, f3);
            } else {
                __half* C = (__half*)Cv;
                *(__half2*)(C + (size_t)r * Nn + c)       = __floats2half2_rn(f0, f1);
                *(__half2*)(C + (size_t)(r + 8) * Nn + c) = __floats2half2_rn(f2, f3);
            }
        }
    }
}

// ---------------- half helpers -------------------------------------------------
__device__ __forceinline__ void h8_acc(float* acc, uint4 v, float w) {
    float2 f0 = __half22float2(*(__half2*)&v.x);
    float2 f1 = __half22float2(*(__half2*)&v.y);
    float2 f2 = __half22float2(*(__half2*)&v.z);
    float2 f3 = __half22float2(*(__half2*)&v.w);
    acc[0] = fmaf(w, f0.x, acc[0]); acc[1] = fmaf(w, f0.y, acc[1]);
    acc[2] = fmaf(w, f1.x, acc[2]); acc[3] = fmaf(w, f1.y, acc[3]);
    acc[4] = fmaf(w, f2.x, acc[4]); acc[5] = fmaf(w, f2.y, acc[5]);
    acc[6] = fmaf(w, f3.x, acc[6]); acc[7] = fmaf(w, f3.y, acc[7]);
}
__device__ __forceinline__ uint4 f8_to_h8(const float* a) {
    __half2 h0 = __floats2half2_rn(a[0], a[1]);
    __half2 h1 = __floats2half2_rn(a[2], a[3]);
    __half2 h2 = __floats2half2_rn(a[4], a[5]);
    __half2 h3 = __floats2half2_rn(a[6], a[7]);
    uint4 r;
    r.x = *(uint32_t*)&h0; r.y = *(uint32_t*)&h1;
    r.z = *(uint32_t*)&h2; r.w = *(uint32_t*)&h3;
    return r;
}

// ---------------- layer-1 aggregation: fp32 x in, fp16 out --------------------
// D=128 floats; 32 threads/node (float4), 4 nodes/block
__global__ void aggp1_kernel(const float* __restrict__ x, __half* __restrict__ hout)
{
    int n = blockIdx.x * 4 + (threadIdx.x >> 5);
    int t = threadIdx.x & 31;
    const float4* h4 = (const float4*)x;

    float din = g_dinv[n], wself = din * din;
    float4 a = h4[(size_t)n * 32 + t];
    float acc[4] = {a.x * wself, a.y * wself, a.z * wself, a.w * wself};

    int e = g_rowptr[n], end = g_rowptr[n + 1];
    for (; e + 4 <= end; e += 4) {
        int s0 = g_colsrc[e], s1 = g_colsrc[e+1], s2 = g_colsrc[e+2], s3 = g_colsrc[e+3];
        float w0 = g_normv[e], w1 = g_normv[e+1], w2 = g_normv[e+2], w3 = g_normv[e+3];
        float4 v0 = h4[(size_t)s0 * 32 + t];
        float4 v1 = h4[(size_t)s1 * 32 + t];
        float4 v2 = h4[(size_t)s2 * 32 + t];
        float4 v3 = h4[(size_t)s3 * 32 + t];
        acc[0] = fmaf(w0, v0.x, acc[0]); acc[1] = fmaf(w0, v0.y, acc[1]);
        acc[2] = fmaf(w0, v0.z, acc[2]); acc[3] = fmaf(w0, v0.w, acc[3]);
        acc[0] = fmaf(w1, v1.x, acc[0]); acc[1] = fmaf(w1, v1.y, acc[1]);
        acc[2] = fmaf(w1, v1.z, acc[2]); acc[3] = fmaf(w1, v1.w, acc[3]);
        acc[0] = fmaf(w2, v2.x, acc[0]); acc[1] = fmaf(w2, v2.y, acc[1]);
        acc[2] = fmaf(w2, v2.z, acc[2]); acc[3] = fmaf(w2, v2.w, acc[3]);
        acc[0] = fmaf(w3, v3.x, acc[0]); acc[1] = fmaf(w3, v3.y, acc[1]);
        acc[2] = fmaf(w3, v3.z, acc[2]); acc[3] = fmaf(w3, v3.w, acc[3]);
    }
    for (; e < end; e++) {
        int s0 = g_colsrc[e]; float w0 = g_normv[e];
        float4 v0 = h4[(size_t)s0 * 32 + t];
        acc[0] = fmaf(w0, v0.x, acc[0]); acc[1] = fmaf(w0, v0.y, acc[1]);
        acc[2] = fmaf(w0, v0.z, acc[2]); acc[3] = fmaf(w0, v0.w, acc[3]);
    }
    __half2 h0 = __floats2half2_rn(acc[0], acc[1]);
    __half2 h1 = __floats2half2_rn(acc[2], acc[3]);
    uint2 o; o.x = *(uint32_t*)&h0; o.y = *(uint32_t*)&h1;
    ((uint2*)hout)[(size_t)n * 32 + t] = o;
}

// ---------------- fp16 aggregation (plain): D halves per row -------------------
template <int D>
__global__ void aggh_kernel(const __half* __restrict__ hin, __half* __restrict__ hout)
{
    const int VT = D / 8;
    const int NPB = 128 / VT;
    int n = blockIdx.x * NPB + threadIdx.x / VT;
    int t = threadIdx.x % VT;
    const uint4* h4 = (const uint4*)hin;

    float acc[8] = {0, 0, 0, 0, 0, 0, 0, 0};
    float din = g_dinv[n];
    h8_acc(acc, h4[(size_t)n * VT + t], din * din);

    int e = g_rowptr[n], end = g_rowptr[n + 1];
    for (; e + 4 <= end; e += 4) {
        int s0 = g_colsrc[e], s1 = g_colsrc[e+1], s2 = g_colsrc[e+2], s3 = g_colsrc[e+3];
        float w0 = g_normv[e], w1 = g_normv[e+1], w2 = g_normv[e+2], w3 = g_normv[e+3];
        uint4 v0 = h4[(size_t)s0 * VT + t];
        uint4 v1 = h4[(size_t)s1 * VT + t];
        uint4 v2 = h4[(size_t)s2 * VT + t];
        uint4 v3 = h4[(size_t)s3 * VT + t];
        h8_acc(acc, v0, w0); h8_acc(acc, v1, w1);
        h8_acc(acc, v2, w2); h8_acc(acc, v3, w3);
    }
    for (; e < end; e++) {
        h8_acc(acc, h4[(size_t)g_colsrc[e] * VT + t], g_normv[e]);
    }
    ((uint4*)hout)[(size_t)n * VT + t] = f8_to_h8(acc);
}

// ---------------- fp16 aggregation with bn(relu(+bias)) epilogue (D=256) -------
__global__ void agghbn_kernel(const __half* __restrict__ hin, __half* __restrict__ hout,
                              const float* __restrict__ bias, const float* __restrict__ gam,
                              const float* __restrict__ bet,  const float* __restrict__ mu,
                              const float* __restrict__ var)
{
    const int VT = 32;                 // 256/8
    int n = blockIdx.x * 4 + threadIdx.x / VT;
    int t = threadIdx.x % VT;
    const uint4* h4 = (const uint4*)hin;

    float acc[8] = {0, 0, 0, 0, 0, 0, 0, 0};
    float din = g_dinv[n];
    h8_acc(acc, h4[(size_t)n * VT + t], din * din);

    int e = g_rowptr[n], end = g_rowptr[n + 1];
    for (; e + 4 <= end; e += 4) {
        int s0 = g_colsrc[e], s1 = g_colsrc[e+1], s2 = g_colsrc[e+2], s3 = g_colsrc[e+3];
        float w0 = g_normv[e], w1 = g_normv[e+1], w2 = g_normv[e+2], w3 = g_normv[e+3];
        uint4 v0 = h4[(size_t)s0 * VT + t];
        uint4 v1 = h4[(size_t)s1 * VT + t];
        uint4 v2 = h4[(size_t)s2 * VT + t];
        uint4 v3 = h4[(size_t)s3 * VT + t];
        h8_acc(acc, v0, w0); h8_acc(acc, v1, w1);
        h8_acc(acc, v2, w2); h8_acc(acc, v3, w3);
    }
    for (; e < end; e++) {
        h8_acc(acc, h4[(size_t)g_colsrc[e] * VT + t], g_normv[e]);
    }

    int c = t * 8;
#pragma unroll
    for (int half8 = 0; half8 < 2; half8++) {
        float4 b4 = *(const float4*)(bias + c + half8 * 4);
        float4 gg = *(const float4*)(gam + c + half8 * 4);
        float4 bb = *(const float4*)(bet + c + half8 * 4);
        float4 mm = *(const float4*)(mu + c + half8 * 4);
        float4 vv = *(const float4*)(var + c + half8 * 4);
        float* a = acc + half8 * 4;
        a[0] = gg.x * (fmaxf(a[0] + b4.x, 0.f) - mm.x) * rsqrtf(vv.x + BN_EPS) + bb.x;
        a[1] = gg.y * (fmaxf(a[1] + b4.y, 0.f) - mm.y) * rsqrtf(vv.y + BN_EPS) + bb.y;
        a[2] = gg.z * (fmaxf(a[2] + b4.z, 0.f) - mm.z) * rsqrtf(vv.z + BN_EPS) + bb.z;
        a[3] = gg.w * (fmaxf(a[3] + b4.w, 0.f) - mm.w) * rsqrtf(vv.w + BN_EPS) + bb.w;
    }
    ((uint4*)hout)[(size_t)n * VT + t] = f8_to_h8(acc);
}

// ---------------- mean pool over sorted batch (fp16 in/out) --------------------
__device__ __forceinline__ int lowerb(const int* __restrict__ b, int n, int v) {
    int lo = 0, hi = n;
    while (lo < hi) {
        int m = (lo + hi) >> 1;
        if (b[m] < v) lo = m + 1; else hi = m;
    }
    return lo;
}

__global__ void pool_kernel(const __half* __restrict__ h, const int* __restrict__ batch,
                            __half* __restrict__ pooled)
{
    int g = blockIdx.x * 4 + (threadIdx.x >> 5);
    int t = threadIdx.x & 31;
    int lo = lowerb(batch, N_NODES, g);
    int hi = lowerb(batch, N_NODES, g + 1);
    const uint4* h4 = (const uint4*)h;
    float acc[8] = {0, 0, 0, 0, 0, 0, 0, 0};
    for (int r = lo; r < hi; r++) h8_acc(acc, h4[(size_t)r * 32 + t], 1.0f);
    float inv = 1.f / fmaxf((float)(hi - lo), 1.f);
#pragma unroll
    for (int i = 0; i < 8; i++) acc[i] *= inv;
    ((uint4*)pooled)[(size_t)g * 32 + t] = f8_to_h8(acc);
}

// ---------------- launch ------------------------------------------------------
extern "C" void kernel_launch(void* const* d_in, const int* in_sizes, int n_in,
                              void* d_out, int out_size)
{
    const float* x   = (const float*)d_in[0];
    const int*   ei  = (const int*)d_in[1];
    const int*   bat = (const int*)d_in[2];
    const float* W1  = (const float*)d_in[3];
    const float* b1  = (const float*)d_in[4];
    const float* W2  = (const float*)d_in[5];
    const float* b2  = (const float*)d_in[6];
    const float* W3  = (const float*)d_in[7];
    const float* b3  = (const float*)d_in[8];
    const float* g1  = (const float*)d_in[9];
    const float* be1 = (const float*)d_in[10];
    const float* m1  = (const float*)d_in[11];
    const float* v1  = (const float*)d_in[12];
    const float* g2  = (const float*)d_in[13];
    const float* be2 = (const float*)d_in[14];
    const float* m2  = (const float*)d_in[15];
    const float* v2  = (const float*)d_in[16];
    const float* g3  = (const float*)d_in[17];
    const float* be3 = (const float*)d_in[18];
    const float* m3  = (const float*)d_in[19];
    const float* v3  = (const float*)d_in[20];
    const float* Wf1 = (const float*)d_in[21];
    const float* bf1 = (const float*)d_in[22];
    const float* Wf2 = (const float*)d_in[23];
    const float* bf2 = (const float*)d_in[24];

    const int* src = ei;
    const int* dst = ei + N_EDGES;

    float *bufA, *bufB, *pooled, *f1, *wr;
    cudaGetSymbolAddress((void**)&bufA,   g_bufA);
    cudaGetSymbolAddress((void**)&bufB,   g_bufB);
    cudaGetSymbolAddress((void**)&pooled, g_pooled);
    cudaGetSymbolAddress((void**)&f1,     g_f1);
    cudaGetSymbolAddress((void**)&wr,     g_wr);

    __half* bufAh   = (__half*)bufA;
    __half* bufBh   = (__half*)bufB;
    __half* pooledh = (__half*)pooled;
    __half* f1h     = (__half*)f1;
    __half* wh      = (__half*)wr;

    // ---- graph preprocessing + weight transpose/fp16 ----
    zero_degc_kernel<<<N_NODES / 256, 256>>>();
    count_kernel<<<N_EDGES / 256, 256>>>(dst);
    scan_p1_kernel<<<128, 1024>>>();
    scan_p2_kernel<<<1, 128>>>();
    scan_p3_kernel<<<N_NODES / 256, 256>>>();
    fill_kernel<<<N_EDGES / 256, 256>>>(src, dst);
    round_w_kernel<<<(NWTOT + 255) / 256, 256>>>(W1, W2, W3, Wf1, Wf2);

    // ---- layer 1: agg(x fp32) -> fp16 -> GEMM 128->512 fused bias+relu+bn ----
    aggp1_kernel<<<N_NODES / 4, 128>>>(x, bufAh);
    hgemm_kernel<<<dim3(DIM_H / 128, N_NODES / 128), 256>>>(
        bufAh, wh + OW1, bufBh, N_NODES, DIM_H, DIM_IN, b1, g1, be1, m1, v1, 1, 0);

    // ---- layer 2: agg fp16 [512] -> GEMM 512->512 fused epilogue ----
    aggh_kernel<DIM_H><<<N_NODES / 2, 128>>>(bufBh, bufAh);
    hgemm_kernel<<<dim3(DIM_H / 128, N_NODES / 128), 256>>>(
        bufAh, wh + OW2, bufBh, N_NODES, DIM_H, DIM_H, b2, g2, be2, m2, v2, 1, 0);

    // ---- layer 3: GEMM 512->256 plain -> agg [256] with epilogue ----
    hgemm_kernel<<<dim3(DIM_OUT / 128, N_NODES / 128), 256>>>(
        bufBh, wh + OW3, bufAh, N_NODES, DIM_OUT, DIM_H,
        nullptr, nullptr, nullptr, nullptr, nullptr, 0, 0);
    agghbn_kernel<<<N_NODES / 4, 128>>>(bufAh, bufBh, b3, g3, be3, m3, v3);

    // ---- mean pool ----
    pool_kernel<<<N_GRAPHS / 4, 128>>>(bufBh, bat, pooledh);

    // ---- MLP head (fp16 hidden, fp32 final out) ----
    hgemm_kernel<<<dim3(DIM_OUT / 128, N_GRAPHS / 128), 256>>>(
        pooledh, wh + OWF1, f1h, N_GRAPHS, DIM_OUT, DIM_OUT,
        bf1, nullptr, nullptr, nullptr, nullptr, 1, 0);
    hgemm_kernel<<<dim3(DIM_OUT / 128, N_GRAPHS / 128), 256>>>(
        f1h, wh + OWF2, d_out, N_GRAPHS, DIM_OUT, DIM_OUT,
        bf2, nullptr, nullptr, nullptr, nullptr, 0, 1);
}